// round 13
// baseline (speedup 1.0000x reference)
#include <cuda_runtime.h>
#include <math.h>

// ---- fixed problem dims (setup_inputs) ----
#define BB   2
#define NN   4096
#define RR   (BB*NN)        // 8192 rays
#define HH   64             // plane H = W
#define DD   48             // coarse samples
#define NIMP 48             // importance samples
#define STOT (DD+NIMP)      // 96
#define NPL  32             // planes
#define NCH  32             // rgb channels
#define FD   160            // feature dim
#define HID  64
#define OD   33
#define MIMP (DD-3)         // 45 pdf bins
#define PI_D 3.14159265358979323846

typedef unsigned long long u64;

// ---- scratch (device globals: no allocations allowed) ----
__device__ float g_poses[NPL*12];
__device__ float g_planesP[BB*NPL*HH*HH*4];   // [B,32,H,W] float4 texels (plane-major)
__device__ float g_depths[RR*STOT];
__device__ float g_sigma[RR*STOT];
__device__ float g_colors[RR*STOT*NCH];
__device__ float g_wf[RR*(STOT-1)];
__device__ float g_cdf[RR*(MIMP+1)];
__device__ unsigned char g_sidx[RR*STOT];     // merged order: g_sidx[ray*96+pos] = orig idx
__device__ unsigned int g_dmin_bits;
__device__ unsigned int g_dmax_bits;
__device__ __align__(16) u64 g_W2p[HID*18];   // packed W2 pairs (staging for constant)
__device__ __align__(16) u64 g_B2p[17];

// MLP weights: warp-uniform reads -> constant/uniform port, off L1
__constant__ __align__(16) float cW1f[FD*HID];   // 40KB
__constant__ __align__(16) float cB1f[HID];
__constant__ __align__(16) u64   cW2p[HID*18];   // 9KB
__constant__ __align__(16) u64   cB2p[17];

__device__ __forceinline__ float softplusf(float x){          // precise (tail kernels)
    return fmaxf(x, 0.f) + log1pf(expf(-fabsf(x)));
}
__device__ __forceinline__ float softplus_fast(float x){      // k_pass
    return fmaxf(x, 0.f) + __logf(1.f + __expf(-fabsf(x)));
}
__device__ __forceinline__ float decode_rgb_fast(float a){
    return __fdividef(1.002f, 1.f + __expf(-a)) - 0.001f;
}

__device__ __forceinline__ void ffma2(u64& acc, u64 ab, u64 w){
    asm("fma.rn.f32x2 %0, %1, %2, %0;" : "+l"(acc) : "l"(ab), "l"(w));
}
__device__ __forceinline__ u64 packf2(float f){
    u64 r; asm("mov.b64 %0, {%1, %1};" : "=l"(r) : "f"(f)); return r;
}
__device__ __forceinline__ u64 pack2(float a, float b){
    u64 r; asm("mov.b64 %0, {%1, %2};" : "=l"(r) : "f"(a), "f"(b)); return r;
}
__device__ __forceinline__ void unpack2(u64 v, float& a, float& b){
    asm("mov.b64 {%0, %1}, %2;" : "=f"(a), "=f"(b) : "l"(v));
}

__device__ __forceinline__ void warp_minmax_atomic(float v){
    unsigned lo = __float_as_uint(v), hi = lo;   // depths > 0: uint order == float order
    #pragma unroll
    for (int o=16;o;o>>=1){
        lo = min(lo, __shfl_xor_sync(0xffffffffu, lo, o));
        hi = max(hi, __shfl_xor_sync(0xffffffffu, hi, o));
    }
    if ((threadIdx.x & 31) == 0){ atomicMin(&g_dmin_bits, lo); atomicMax(&g_dmax_bits, hi); }
}

__device__ void mm4(const double* A, const double* B, double* C){
    #pragma unroll
    for (int r=0;r<4;r++)
    #pragma unroll
    for (int c=0;c<4;c++){
        double s=0.0;
        #pragma unroll
        for (int k=0;k<4;k++) s += A[r*4+k]*B[k*4+c];
        C[r*4+c]=s;
    }
}

// ---- camera pose constants, computed in double to match numpy ----
__global__ void k_poses(){
    int i = threadIdx.x;
    if (i == 0){ g_dmin_bits = 0x7f800000u; g_dmax_bits = 0u; }
    if (i >= NPL) return;
    double y  = 1.0 - (i/31.0)*2.0;
    double r  = sqrt(1.0 - y*y);
    double golden = PI_D * (sqrt(5.0) - 1.0);
    double th = golden * (double)i;
    double x  = cos(th)*r, z = sin(th)*r;
    double phi   = atan2(z, sqrt(x*x + y*y));
    double theta = atan2(y, x);
    double radius = -1.307;
    double p = phi/180.0*PI_D;
    double t = theta/180.0*PI_D;
    double e = 90.0/180.0*PI_D;

    double Tm[16]={1,0,0,0, 0,1,0,0, 0,0,1,radius, 0,0,0,1};
    double Pm[16]={1,0,0,0, 0,cos(p),-sin(p),0, 0,sin(p),cos(p),0, 0,0,0,1};
    double Th[16]={cos(t),0,-sin(t),0, 0,1,0,0, sin(t),0,cos(t),0, 0,0,0,1};
    double Em[16]={cos(e),sin(e),0,0, -sin(e),cos(e),0,0, 0,0,1,0, 0,0,0,1};
    double Fm[16]={-1,0,0,0, 0,0,1,0, 0,1,0,0, 0,0,0,1};
    double t1[16], t2[16];
    mm4(Pm,Tm,t1); mm4(Th,t1,t2); mm4(Em,t2,t1); mm4(Fm,t1,t2);   // t2 = c2w
    double A[16];
    #pragma unroll
    for (int rr=0;rr<4;rr++){
        A[rr*4+0] = -t2[rr*4+0];
        A[rr*4+1] =  t2[rr*4+1];
        A[rr*4+2] =  t2[rr*4+2];
        A[rr*4+3] =  t2[rr*4+3];
    }
    #pragma unroll
    for (int rr=0;rr<3;rr++){
        g_poses[i*12 + rr*4 + 0] = (float)A[0*4+rr];
        g_poses[i*12 + rr*4 + 1] = (float)A[1*4+rr];
        g_poses[i*12 + rr*4 + 2] = (float)A[2*4+rr];
        double tr = -(A[0*4+rr]*A[0*4+3] + A[1*4+rr]*A[1*4+3] + A[2*4+rr]*A[2*4+3]);
        g_poses[i*12 + rr*4 + 3] = (float)tr;
    }
}

// ---- pack W2/B2 into padded u64 pair tables (staged, then copied to constant) ----
__global__ void k_prepW2(const float* __restrict__ W2g, const float* __restrict__ B2g){
    int i = blockIdx.x*blockDim.x + threadIdx.x;
    if (i < HID*18){
        int j = i/18, p = i - j*18;
        float lo = (p < 17) ? W2g[j*OD + 2*p] : 0.f;
        float hi = (p < 16) ? W2g[j*OD + 2*p+1] : 0.f;
        g_W2p[i] = pack2(lo, hi);
    }
    if (i < 17) g_B2p[i] = pack2(B2g[2*i], (i<16)? B2g[2*i+1] : 0.f);
}

// ---- planes [B,96,H,W] -> [B,32,H,W] float4 (plane-major texels) ----
__global__ void k_transpose(const float* __restrict__ planes){
    int i = blockIdx.x*blockDim.x + threadIdx.x;
    if (i >= BB*NPL*HH*HH) return;
    int x  = i & 63; int t = i >> 6;
    int yy = t & 63; t >>= 6;
    int kk = t & 31; int b = t >> 5;
    float4 v;
    v.x = planes[((b*96 + 3*kk+0)*HH + yy)*HH + x];
    v.y = planes[((b*96 + 3*kk+1)*HH + yy)*HH + x];
    v.z = planes[((b*96 + 3*kk+2)*HH + yy)*HH + x];
    v.w = 0.f;
    reinterpret_cast<float4*>(g_planesP)[i] = v;
}

__global__ void k_depths(const float* __restrict__ noise){
    int i = blockIdx.x*blockDim.x + threadIdx.x;
    if (i >= RR*DD) return;
    int s = i % DD; int ray = i / DD;
    const float step = (2.5f - 0.5f)/(float)(DD-1);
    float d = 0.5f + (float)s*step + noise[i]*step;
    g_depths[ray*STOT + s] = d;
    warp_minmax_atomic(d);
}

// ---- fused gather+MLP, hidden dim split into 2 halves for occupancy ----
__global__ void __launch_bounds__(128, 6) k_pass(const float* __restrict__ ro,
                                                 const float* __restrict__ rd,
                                                 int scol0){
    __shared__ __align__(16) float sPoses[NPL*12];
    __shared__ __align__(16) u64   sAcc2[17*128];   // layer-2 partials parked between halves
    int tid = threadIdx.x;
    for (int i = tid; i < NPL*12; i += 128) sPoses[i] = g_poses[i];
    __syncthreads();

    int q = blockIdx.x*128 + tid;                 // point index, samples fastest
    int b   = q / (NN*DD);
    int rem = q - b*(NN*DD);
    int n   = rem / DD;
    int s   = rem - n*DD;
    int ray = b*NN + n;
    int base = ray*STOT + scol0 + s;

    float depth = g_depths[base];
    float ox = ro[ray*3+0], oy = ro[ray*3+1], oz = ro[ray*3+2];
    float dx = rd[ray*3+0], dy = rd[ray*3+1], dz = rd[ray*3+2];
    float px = fmaf(depth,dx,ox), py = fmaf(depth,dy,oy), pz = fmaf(depth,dz,oz);
    const float4* planeB = reinterpret_cast<const float4*>(g_planesP) + b*(NPL*HH*HH);

    #pragma unroll 1
    for (int half=0; half<2; half++){
        int hb = half*32;                          // hidden-unit base for this half

        u64 acc[16];
        {
            const ulonglong2* b2 = reinterpret_cast<const ulonglong2*>(&cB1f[hb]);
            #pragma unroll
            for (int p=0;p<8;p++){ ulonglong2 bp = b2[p]; acc[2*p] = bp.x; acc[2*p+1] = bp.y; }
        }

        #pragma unroll 1
        for (int kk=0; kk<NPL; kk++){
            const float* P = sPoses + kk*12;
            float cx = fmaf(P[0],px, fmaf(P[1],py, fmaf(P[2],pz,  P[3])));
            float cy = fmaf(P[4],px, fmaf(P[5],py, fmaf(P[6],pz,  P[7])));
            float cz = fmaf(P[8],px, fmaf(P[9],py, fmaf(P[10],pz, P[11])));
            float gx = fminf(fmaxf((1.0254f*cx + 0.5f*cz)/cz, 0.f), 1.f)*2.f - 1.f;
            float gy = fminf(fmaxf((1.0254f*cy + 0.5f*cz)/cz, 0.f), 1.f)*2.f - 1.f;
            float ix = ((gx + 1.f)*(float)HH - 1.f)*0.5f;
            float iy = ((gy + 1.f)*(float)HH - 1.f)*0.5f;
            float x0 = floorf(ix), y0 = floorf(iy);
            float wx = ix - x0,    wy = iy - y0;
            float vx0 = (x0 >= 0.f)  ? 1.f : 0.f;
            float vx1 = (x0 <= 62.f) ? 1.f : 0.f;
            float vy0 = (y0 >= 0.f)  ? 1.f : 0.f;
            float vy1 = (y0 <= 62.f) ? 1.f : 0.f;
            int x0i = (int)x0, y0i = (int)y0;
            int x0c = max(x0i, 0),   y0c = max(y0i, 0);
            int x1c = min(x0i+1,63), y1c = min(y0i+1,63);
            float w00 = (1.f-wx)*(1.f-wy)*vx0*vy0;
            float w10 = wx*(1.f-wy)*vx1*vy0;
            float w01 = (1.f-wx)*wy*vx0*vy1;
            float w11 = wx*wy*vx1*vy1;
            const float4* planeK = planeB + kk*(HH*HH);
            float4 t00 = planeK[y0c*HH + x0c];
            float4 t10 = planeK[y0c*HH + x1c];
            float4 t01 = planeK[y1c*HH + x0c];
            float4 t11 = planeK[y1c*HH + x1c];

            {
                u64 ff = packf2(gx);
                const ulonglong2* w2 = reinterpret_cast<const ulonglong2*>(&cW1f[(96+2*kk)*HID + hb]);
                #pragma unroll
                for (int p=0;p<8;p++){ ulonglong2 wp = w2[p]; ffma2(acc[2*p],ff,wp.x); ffma2(acc[2*p+1],ff,wp.y); }
            }
            {
                u64 ff = packf2(gy);
                const ulonglong2* w2 = reinterpret_cast<const ulonglong2*>(&cW1f[(96+2*kk+1)*HID + hb]);
                #pragma unroll
                for (int p=0;p<8;p++){ ulonglong2 wp = w2[p]; ffma2(acc[2*p],ff,wp.x); ffma2(acc[2*p+1],ff,wp.y); }
            }
            float c0 = t00.x*w00 + t10.x*w10 + t01.x*w01 + t11.x*w11;
            float c1 = t00.y*w00 + t10.y*w10 + t01.y*w01 + t11.y*w11;
            float c2 = t00.z*w00 + t10.z*w10 + t01.z*w01 + t11.z*w11;
            {
                u64 ff = packf2(c0);
                const ulonglong2* w2 = reinterpret_cast<const ulonglong2*>(&cW1f[(3*kk+0)*HID + hb]);
                #pragma unroll
                for (int p=0;p<8;p++){ ulonglong2 wp = w2[p]; ffma2(acc[2*p],ff,wp.x); ffma2(acc[2*p+1],ff,wp.y); }
            }
            {
                u64 ff = packf2(c1);
                const ulonglong2* w2 = reinterpret_cast<const ulonglong2*>(&cW1f[(3*kk+1)*HID + hb]);
                #pragma unroll
                for (int p=0;p<8;p++){ ulonglong2 wp = w2[p]; ffma2(acc[2*p],ff,wp.x); ffma2(acc[2*p+1],ff,wp.y); }
            }
            {
                u64 ff = packf2(c2);
                const ulonglong2* w2 = reinterpret_cast<const ulonglong2*>(&cW1f[(3*kk+2)*HID + hb]);
                #pragma unroll
                for (int p=0;p<8;p++){ ulonglong2 wp = w2[p]; ffma2(acc[2*p],ff,wp.x); ffma2(acc[2*p+1],ff,wp.y); }
            }
        }

        // layer-2 partial accumulation for this half's 32 hidden units
        u64 acc2[17];
        if (half == 0){
            #pragma unroll
            for (int p=0;p<17;p++) acc2[p] = cB2p[p];
        } else {
            #pragma unroll
            for (int p=0;p<17;p++) acc2[p] = sAcc2[p*128 + tid];
        }
        #pragma unroll
        for (int jh=0; jh<16; jh++){
            float a, bb;
            unpack2(acc[jh], a, bb);
            int u0 = hb + 2*jh;
            {
                u64 ha = packf2(softplus_fast(a));
                const ulonglong2* w2 = reinterpret_cast<const ulonglong2*>(&cW2p[u0*18]);
                #pragma unroll
                for (int p=0;p<8;p++){ ulonglong2 wp = w2[p]; ffma2(acc2[2*p],ha,wp.x); ffma2(acc2[2*p+1],ha,wp.y); }
                ffma2(acc2[16], ha, cW2p[u0*18 + 16]);
            }
            {
                u64 hb2 = packf2(softplus_fast(bb));
                const ulonglong2* w2 = reinterpret_cast<const ulonglong2*>(&cW2p[(u0+1)*18]);
                #pragma unroll
                for (int p=0;p<8;p++){ ulonglong2 wp = w2[p]; ffma2(acc2[2*p],hb2,wp.x); ffma2(acc2[2*p+1],hb2,wp.y); }
                ffma2(acc2[16], hb2, cW2p[(u0+1)*18 + 16]);
            }
        }
        if (half == 0){
            #pragma unroll
            for (int p=0;p<17;p++) sAcc2[p*128 + tid] = acc2[p];
        } else {
            float ov[34];
            #pragma unroll
            for (int p=0;p<17;p++) unpack2(acc2[p], ov[2*p], ov[2*p+1]);
            g_sigma[base] = ov[0];
            float4* cdst = reinterpret_cast<float4*>(g_colors + (size_t)base*NCH);
            #pragma unroll
            for (int t=0;t<8;t++){
                float4 v;
                v.x = decode_rgb_fast(ov[1+4*t+0]);
                v.y = decode_rgb_fast(ov[1+4*t+1]);
                v.z = decode_rgb_fast(ov[1+4*t+2]);
                v.w = decode_rgb_fast(ov[1+4*t+3]);
                cdst[t] = v;
            }
        }
    }
}

// ---- fused coarse march + pdf smoothing + cdf (per-ray, weights stay in regs) ----
__global__ void k_cmarch_cdf(){
    int ray = blockIdx.x*blockDim.x + threadIdx.x;
    if (ray >= RR) return;
    const float* dep = g_depths + ray*STOT;
    const float* sig = g_sigma  + ray*STOT;
    float w[DD-1];
    float T = 1.f;
    float sp = sig[0], dp = dep[0];
    #pragma unroll 1
    for (int s=1; s<DD; s++){
        float sc = sig[s], dc = dep[s];
        float delta = dc - dp;
        float dm = softplusf(0.5f*(sp+sc) - 1.f);
        float alpha = 1.f - expf(-dm*delta);
        w[s-1] = alpha*T;
        T *= (1.f - alpha + 1e-10f);
        sp = sc; dp = dc;
    }
    float m[DD];
    m[0] = w[0]; m[DD-1] = w[DD-2];
    #pragma unroll 1
    for (int i=1;i<DD-1;i++) m[i] = fmaxf(w[i-1], w[i]);
    float pw[MIMP]; float tot = 0.f;
    #pragma unroll 1
    for (int i=0;i<MIMP;i++){
        pw[i] = 0.5f*(m[i+1] + m[i+2]) + 0.01f + 1e-5f;
        tot += pw[i];
    }
    float* cdf = g_cdf + ray*(MIMP+1);
    cdf[0] = 0.f;
    float run = 0.f;
    #pragma unroll 1
    for (int i=0;i<MIMP;i++){ run += pw[i]/tot; cdf[i+1] = run; }
}

// per-sample: searchsorted-right (upper_bound) + interp; folds fine-depth minmax
__global__ void k_sample(const float* __restrict__ u){
    int idx = blockIdx.x*blockDim.x + threadIdx.x;
    if (idx >= RR*NIMP) return;
    int ray = idx / NIMP, t = idx - ray*NIMP;
    float uu = u[idx];
    const float* cdf = g_cdf + ray*(MIMP+1);
    int lo = 0, hi = MIMP+1;           // first index with cdf[i] > u
    while (lo < hi){
        int mid = (lo + hi) >> 1;
        if (cdf[mid] <= uu) lo = mid + 1; else hi = mid;
    }
    int ind = lo;
    int below = max(ind-1, 0);
    int above = min(ind, MIMP);
    float cb = cdf[below], ca = cdf[above];
    const float* z = g_depths + ray*STOT;
    float bb = z[below], ba = z[above];
    float denom = ca - cb;
    if (denom < 1e-5f) denom = 1.f;
    float zf = bb + (uu - cb)/denom*(ba - bb);
    g_depths[ray*STOT + DD + t] = zf;
    warp_minmax_atomic(zf);
}

// ---- parallel stable-merge order: one thread per (ray, sample) ----
__global__ void k_order(){
    int idx = blockIdx.x*blockDim.x + threadIdx.x;
    if (idx >= RR*STOT) return;
    int ray = idx / STOT, i = idx - ray*STOT;
    const float* dep = g_depths + ray*STOT;
    int pos;
    if (i < DD){
        float z = dep[i];
        int cnt = 0;
        #pragma unroll 1
        for (int j=0;j<NIMP;j++) cnt += (dep[DD+j] < z) ? 1 : 0;
        pos = i + cnt;
    } else {
        int t = i - DD;
        float z = dep[i];
        int cc = 0;
        #pragma unroll 1
        for (int s=0;s<DD;s++) cc += (dep[s] <= z) ? 1 : 0;
        int cf = 0;
        #pragma unroll 1
        for (int j=0;j<NIMP;j++){
            float zj = dep[DD+j];
            cf += (zj < z || (zj == z && j < t)) ? 1 : 0;
        }
        pos = cc + cf;
    }
    g_sidx[ray*STOT + pos] = (unsigned char)i;
}

// ---- final march over precomputed order (no sort) ----
__global__ void k_march(float* __restrict__ out){
    int ray = blockIdx.x*blockDim.x + threadIdx.x;
    if (ray >= RR) return;
    const float* dep = g_depths + ray*STOT;
    const float* sig = g_sigma  + ray*STOT;
    const unsigned char* ord = g_sidx + ray*STOT;
    float T = 1.f, wtot = 0.f, dsum = 0.f;
    int ip = ord[0];
    float dprev = dep[ip], sp = sig[ip];
    #pragma unroll 1
    for (int s=1;s<STOT;s++){
        int ic = ord[s];
        float dc = dep[ic], sc = sig[ic];
        float delta = dc - dprev;
        float dm = softplusf(0.5f*(sp+sc) - 1.f);
        float alpha = 1.f - expf(-dm*delta);
        float wgt = alpha*T;
        g_wf[ray*(STOT-1) + s-1] = wgt;
        wtot += wgt;
        dsum += wgt*0.5f*(dprev + dc);
        T *= (1.f - alpha + 1e-10f);
        dprev = dc; sp = sc;
    }
    float depth = dsum/wtot;
    if (isnan(depth)) depth = __int_as_float(0x7f800000);
    float dmin = __uint_as_float(g_dmin_bits), dmax = __uint_as_float(g_dmax_bits);
    depth = fminf(fmaxf(depth, dmin), dmax);
    out[ray*34 + 32] = depth;
    out[ray*34 + 33] = wtot;
}

// channel-vectorized rgb: one thread = 4 channels of one ray
__global__ void k_rgb(float* __restrict__ out){
    int idx = blockIdx.x*blockDim.x + threadIdx.x;
    if (idx >= RR*8) return;
    int c4 = (idx & 7); int ray = idx >> 3;
    const unsigned char* mi = g_sidx + ray*STOT;
    const float4* col = reinterpret_cast<const float4*>(g_colors + (size_t)ray*STOT*NCH);
    const float* wv  = g_wf + ray*(STOT-1);
    float4 acc = make_float4(0.f,0.f,0.f,0.f);
    float4 cp = col[(int)mi[0]*8 + c4];
    #pragma unroll 1
    for (int s=1;s<STOT;s++){
        float4 cc = col[(int)mi[s]*8 + c4];
        float w = wv[s-1]*0.5f;
        acc.x += w*(cp.x + cc.x);
        acc.y += w*(cp.y + cc.y);
        acc.z += w*(cp.z + cc.z);
        acc.w += w*(cp.w + cc.w);
        cp = cc;
    }
    float* o = out + ray*34 + c4*4;
    o[0] = acc.x*2.f - 1.f;
    o[1] = acc.y*2.f - 1.f;
    o[2] = acc.z*2.f - 1.f;
    o[3] = acc.w*2.f - 1.f;
}

extern "C" void kernel_launch(void* const* d_in, const int* in_sizes, int n_in,
                              void* d_out, int out_size){
    const float* planes = (const float*)d_in[0];
    const float* ro     = (const float*)d_in[1];
    const float* rd     = (const float*)d_in[2];
    const float* noise  = (const float*)d_in[3];
    const float* pdfu   = (const float*)d_in[4];
    const float* W2g    = (const float*)d_in[7];
    const float* B2g    = (const float*)d_in[8];
    float* out = (float*)d_out;

    cudaMemcpyToSymbolAsync(cW1f, d_in[5], FD*HID*sizeof(float), 0, cudaMemcpyDeviceToDevice, 0);
    cudaMemcpyToSymbolAsync(cB1f, d_in[6], HID*sizeof(float),    0, cudaMemcpyDeviceToDevice, 0);

    // pack W2/B2 on device, then stage into constant memory
    k_prepW2<<<(HID*18 + 127)/128, 128>>>(W2g, B2g);
    {
        void* pW2 = nullptr; void* pB2 = nullptr;
        cudaGetSymbolAddress(&pW2, g_W2p);
        cudaGetSymbolAddress(&pB2, g_B2p);
        cudaMemcpyToSymbolAsync(cW2p, pW2, HID*18*sizeof(u64), 0, cudaMemcpyDeviceToDevice, 0);
        cudaMemcpyToSymbolAsync(cB2p, pB2, 17*sizeof(u64),     0, cudaMemcpyDeviceToDevice, 0);
    }

    k_poses<<<1, 32>>>();
    k_transpose<<<(BB*NPL*HH*HH + 255)/256, 256>>>(planes);
    k_depths<<<(RR*DD + 255)/256, 256>>>(noise);

    // coarse pass
    k_pass<<<(RR*DD)/128, 128>>>(ro, rd, 0);
    k_cmarch_cdf<<<(RR + 63)/64, 64>>>();
    k_sample<<<(RR*NIMP + 255)/256, 256>>>(pdfu);

    // fine pass (NIMP == DD so the same index math applies)
    k_pass<<<(RR*NIMP)/128, 128>>>(ro, rd, DD);

    // merged order + final march + rgb
    k_order<<<(RR*STOT + 255)/256, 256>>>();
    k_march<<<(RR + 63)/64, 64>>>(out);
    k_rgb<<<(RR*8 + 127)/128, 128>>>(out);
}

// round 14
// speedup vs baseline: 1.0831x; 1.0831x over previous
#include <cuda_runtime.h>
#include <math.h>

// ---- fixed problem dims (setup_inputs) ----
#define BB   2
#define NN   4096
#define RR   (BB*NN)        // 8192 rays
#define HH   64             // plane H = W
#define DD   48             // coarse samples
#define NIMP 48             // importance samples
#define STOT (DD+NIMP)      // 96
#define NPL  32             // planes
#define NCH  32             // rgb channels
#define FD   160            // feature dim
#define HID  64
#define OD   33
#define MIMP (DD-3)         // 45 pdf bins
#define PI_D 3.14159265358979323846

typedef unsigned long long u64;

// ---- scratch (device globals: no allocations allowed) ----
__device__ float g_poses[NPL*12];
__device__ float g_planesP[BB*NPL*HH*HH*4];   // [B,32,H,W] float4 texels (plane-major)
__device__ float g_depths[RR*STOT];
__device__ float g_sigma[RR*STOT];
__device__ float g_colors[RR*STOT*NCH];
__device__ float g_cdf[RR*(MIMP+1)];
__device__ unsigned int g_dmin_bits;
__device__ unsigned int g_dmax_bits;
__device__ __align__(16) u64 g_W2p[HID*18];   // packed W2 pairs (staging for constant)
__device__ __align__(16) u64 g_B2p[17];

// MLP weights: warp-uniform reads -> constant/uniform port, off L1
__constant__ __align__(16) float cW1f[FD*HID];   // 40KB
__constant__ __align__(16) float cB1f[HID];
__constant__ __align__(16) u64   cW2p[HID*18];   // 9KB
__constant__ __align__(16) u64   cB2p[17];

__device__ __forceinline__ float softplusf(float x){          // precise (tail kernels)
    return fmaxf(x, 0.f) + log1pf(expf(-fabsf(x)));
}
__device__ __forceinline__ float softplus_fast(float x){      // k_pass
    return fmaxf(x, 0.f) + __logf(1.f + __expf(-fabsf(x)));
}
__device__ __forceinline__ float decode_rgb_fast(float a){
    return __fdividef(1.002f, 1.f + __expf(-a)) - 0.001f;
}

__device__ __forceinline__ void ffma2(u64& acc, u64 ab, u64 w){
    asm("fma.rn.f32x2 %0, %1, %2, %0;" : "+l"(acc) : "l"(ab), "l"(w));
}
__device__ __forceinline__ u64 packf2(float f){
    u64 r; asm("mov.b64 %0, {%1, %1};" : "=l"(r) : "f"(f)); return r;
}
__device__ __forceinline__ u64 pack2(float a, float b){
    u64 r; asm("mov.b64 %0, {%1, %2};" : "=l"(r) : "f"(a), "f"(b)); return r;
}
__device__ __forceinline__ void unpack2(u64 v, float& a, float& b){
    asm("mov.b64 {%0, %1}, %2;" : "=f"(a), "=f"(b) : "l"(v));
}

__device__ __forceinline__ void warp_minmax_atomic(float v){
    unsigned lo = __float_as_uint(v), hi = lo;   // depths > 0: uint order == float order
    #pragma unroll
    for (int o=16;o;o>>=1){
        lo = min(lo, __shfl_xor_sync(0xffffffffu, lo, o));
        hi = max(hi, __shfl_xor_sync(0xffffffffu, hi, o));
    }
    if ((threadIdx.x & 31) == 0){ atomicMin(&g_dmin_bits, lo); atomicMax(&g_dmax_bits, hi); }
}

__device__ void mm4(const double* A, const double* B, double* C){
    #pragma unroll
    for (int r=0;r<4;r++)
    #pragma unroll
    for (int c=0;c<4;c++){
        double s=0.0;
        #pragma unroll
        for (int k=0;k<4;k++) s += A[r*4+k]*B[k*4+c];
        C[r*4+c]=s;
    }
}

// ---- camera pose constants, computed in double to match numpy ----
__global__ void k_poses(){
    int i = threadIdx.x;
    if (i == 0){ g_dmin_bits = 0x7f800000u; g_dmax_bits = 0u; }
    if (i >= NPL) return;
    double y  = 1.0 - (i/31.0)*2.0;
    double r  = sqrt(1.0 - y*y);
    double golden = PI_D * (sqrt(5.0) - 1.0);
    double th = golden * (double)i;
    double x  = cos(th)*r, z = sin(th)*r;
    double phi   = atan2(z, sqrt(x*x + y*y));
    double theta = atan2(y, x);
    double radius = -1.307;
    double p = phi/180.0*PI_D;
    double t = theta/180.0*PI_D;
    double e = 90.0/180.0*PI_D;

    double Tm[16]={1,0,0,0, 0,1,0,0, 0,0,1,radius, 0,0,0,1};
    double Pm[16]={1,0,0,0, 0,cos(p),-sin(p),0, 0,sin(p),cos(p),0, 0,0,0,1};
    double Th[16]={cos(t),0,-sin(t),0, 0,1,0,0, sin(t),0,cos(t),0, 0,0,0,1};
    double Em[16]={cos(e),sin(e),0,0, -sin(e),cos(e),0,0, 0,0,1,0, 0,0,0,1};
    double Fm[16]={-1,0,0,0, 0,0,1,0, 0,1,0,0, 0,0,0,1};
    double t1[16], t2[16];
    mm4(Pm,Tm,t1); mm4(Th,t1,t2); mm4(Em,t2,t1); mm4(Fm,t1,t2);   // t2 = c2w
    double A[16];
    #pragma unroll
    for (int rr=0;rr<4;rr++){
        A[rr*4+0] = -t2[rr*4+0];
        A[rr*4+1] =  t2[rr*4+1];
        A[rr*4+2] =  t2[rr*4+2];
        A[rr*4+3] =  t2[rr*4+3];
    }
    #pragma unroll
    for (int rr=0;rr<3;rr++){
        g_poses[i*12 + rr*4 + 0] = (float)A[0*4+rr];
        g_poses[i*12 + rr*4 + 1] = (float)A[1*4+rr];
        g_poses[i*12 + rr*4 + 2] = (float)A[2*4+rr];
        double tr = -(A[0*4+rr]*A[0*4+3] + A[1*4+rr]*A[1*4+3] + A[2*4+rr]*A[2*4+3]);
        g_poses[i*12 + rr*4 + 3] = (float)tr;
    }
}

// ---- pack W2/B2 into padded u64 pair tables (staged, then copied to constant) ----
__global__ void k_prepW2(const float* __restrict__ W2g, const float* __restrict__ B2g){
    int i = blockIdx.x*blockDim.x + threadIdx.x;
    if (i < HID*18){
        int j = i/18, p = i - j*18;
        float lo = (p < 17) ? W2g[j*OD + 2*p] : 0.f;
        float hi = (p < 16) ? W2g[j*OD + 2*p+1] : 0.f;
        g_W2p[i] = pack2(lo, hi);
    }
    if (i < 17) g_B2p[i] = pack2(B2g[2*i], (i<16)? B2g[2*i+1] : 0.f);
}

// ---- planes [B,96,H,W] -> [B,32,H,W] float4 (plane-major texels) ----
__global__ void k_transpose(const float* __restrict__ planes){
    int i = blockIdx.x*blockDim.x + threadIdx.x;
    if (i >= BB*NPL*HH*HH) return;
    int x  = i & 63; int t = i >> 6;
    int yy = t & 63; t >>= 6;
    int kk = t & 31; int b = t >> 5;
    float4 v;
    v.x = planes[((b*96 + 3*kk+0)*HH + yy)*HH + x];
    v.y = planes[((b*96 + 3*kk+1)*HH + yy)*HH + x];
    v.z = planes[((b*96 + 3*kk+2)*HH + yy)*HH + x];
    v.w = 0.f;
    reinterpret_cast<float4*>(g_planesP)[i] = v;
}

__global__ void k_depths(const float* __restrict__ noise){
    int i = blockIdx.x*blockDim.x + threadIdx.x;
    if (i >= RR*DD) return;
    int s = i % DD; int ray = i / DD;
    const float step = (2.5f - 0.5f)/(float)(DD-1);
    float d = 0.5f + (float)s*step + noise[i]*step;
    g_depths[ray*STOT + s] = d;
    warp_minmax_atomic(d);
}

// ---- fused feature gather + MLP: one lane = one point (R12 body, unchanged) ----
__global__ void __launch_bounds__(128, 4) k_pass(const float* __restrict__ ro,
                                                 const float* __restrict__ rd,
                                                 int scol0){
    __shared__ __align__(16) float sPoses[NPL*12];
    int tid = threadIdx.x;
    for (int i = tid; i < NPL*12; i += 128) sPoses[i] = g_poses[i];
    __syncthreads();

    int q = blockIdx.x*128 + tid;                 // point index, samples fastest
    int b   = q / (NN*DD);
    int rem = q - b*(NN*DD);
    int n   = rem / DD;
    int s   = rem - n*DD;
    int ray = b*NN + n;
    int base = ray*STOT + scol0 + s;

    float depth = g_depths[base];
    float ox = ro[ray*3+0], oy = ro[ray*3+1], oz = ro[ray*3+2];
    float dx = rd[ray*3+0], dy = rd[ray*3+1], dz = rd[ray*3+2];
    float px = fmaf(depth,dx,ox), py = fmaf(depth,dy,oy), pz = fmaf(depth,dz,oz);
    const float4* planeB = reinterpret_cast<const float4*>(g_planesP) + b*(NPL*HH*HH);

    u64 acc[32];
    {
        const ulonglong2* b2 = reinterpret_cast<const ulonglong2*>(cB1f);
        #pragma unroll
        for (int p=0;p<16;p++){ ulonglong2 bp = b2[p]; acc[2*p] = bp.x; acc[2*p+1] = bp.y; }
    }

    #pragma unroll 1
    for (int kk=0; kk<NPL; kk++){
        const float* P = sPoses + kk*12;
        float cx = fmaf(P[0],px, fmaf(P[1],py, fmaf(P[2],pz,  P[3])));
        float cy = fmaf(P[4],px, fmaf(P[5],py, fmaf(P[6],pz,  P[7])));
        float cz = fmaf(P[8],px, fmaf(P[9],py, fmaf(P[10],pz, P[11])));
        float gx = fminf(fmaxf((1.0254f*cx + 0.5f*cz)/cz, 0.f), 1.f)*2.f - 1.f;
        float gy = fminf(fmaxf((1.0254f*cy + 0.5f*cz)/cz, 0.f), 1.f)*2.f - 1.f;
        float ix = ((gx + 1.f)*(float)HH - 1.f)*0.5f;
        float iy = ((gy + 1.f)*(float)HH - 1.f)*0.5f;
        float x0 = floorf(ix), y0 = floorf(iy);
        float wx = ix - x0,    wy = iy - y0;
        float vx0 = (x0 >= 0.f)  ? 1.f : 0.f;
        float vx1 = (x0 <= 62.f) ? 1.f : 0.f;
        float vy0 = (y0 >= 0.f)  ? 1.f : 0.f;
        float vy1 = (y0 <= 62.f) ? 1.f : 0.f;
        int x0i = (int)x0, y0i = (int)y0;
        int x0c = max(x0i, 0),   y0c = max(y0i, 0);
        int x1c = min(x0i+1,63), y1c = min(y0i+1,63);
        float w00 = (1.f-wx)*(1.f-wy)*vx0*vy0;
        float w10 = wx*(1.f-wy)*vx1*vy0;
        float w01 = (1.f-wx)*wy*vx0*vy1;
        float w11 = wx*wy*vx1*vy1;
        const float4* planeK = planeB + kk*(HH*HH);
        float4 t00 = planeK[y0c*HH + x0c];
        float4 t10 = planeK[y0c*HH + x1c];
        float4 t01 = planeK[y1c*HH + x0c];
        float4 t11 = planeK[y1c*HH + x1c];

        {
            u64 ff = packf2(gx);
            const ulonglong2* w2 = reinterpret_cast<const ulonglong2*>(&cW1f[(96+2*kk)*HID]);
            #pragma unroll
            for (int p=0;p<16;p++){ ulonglong2 wp = w2[p]; ffma2(acc[2*p],ff,wp.x); ffma2(acc[2*p+1],ff,wp.y); }
        }
        {
            u64 ff = packf2(gy);
            const ulonglong2* w2 = reinterpret_cast<const ulonglong2*>(&cW1f[(96+2*kk+1)*HID]);
            #pragma unroll
            for (int p=0;p<16;p++){ ulonglong2 wp = w2[p]; ffma2(acc[2*p],ff,wp.x); ffma2(acc[2*p+1],ff,wp.y); }
        }
        float c0 = t00.x*w00 + t10.x*w10 + t01.x*w01 + t11.x*w11;
        float c1 = t00.y*w00 + t10.y*w10 + t01.y*w01 + t11.y*w11;
        float c2 = t00.z*w00 + t10.z*w10 + t01.z*w01 + t11.z*w11;
        {
            u64 ff = packf2(c0);
            const ulonglong2* w2 = reinterpret_cast<const ulonglong2*>(&cW1f[(3*kk+0)*HID]);
            #pragma unroll
            for (int p=0;p<16;p++){ ulonglong2 wp = w2[p]; ffma2(acc[2*p],ff,wp.x); ffma2(acc[2*p+1],ff,wp.y); }
        }
        {
            u64 ff = packf2(c1);
            const ulonglong2* w2 = reinterpret_cast<const ulonglong2*>(&cW1f[(3*kk+1)*HID]);
            #pragma unroll
            for (int p=0;p<16;p++){ ulonglong2 wp = w2[p]; ffma2(acc[2*p],ff,wp.x); ffma2(acc[2*p+1],ff,wp.y); }
        }
        {
            u64 ff = packf2(c2);
            const ulonglong2* w2 = reinterpret_cast<const ulonglong2*>(&cW1f[(3*kk+2)*HID]);
            #pragma unroll
            for (int p=0;p<16;p++){ ulonglong2 wp = w2[p]; ffma2(acc[2*p],ff,wp.x); ffma2(acc[2*p+1],ff,wp.y); }
        }
    }

    // layer 2 + decode, fully in registers (W2 via constant port)
    u64 acc2[17];
    #pragma unroll
    for (int p=0;p<17;p++) acc2[p] = cB2p[p];
    #pragma unroll
    for (int jh=0; jh<32; jh++){
        float a, bb;
        unpack2(acc[jh], a, bb);
        {
            u64 ha = packf2(softplus_fast(a));
            const ulonglong2* w2 = reinterpret_cast<const ulonglong2*>(&cW2p[(2*jh)*18]);
            #pragma unroll
            for (int p=0;p<8;p++){ ulonglong2 wp = w2[p]; ffma2(acc2[2*p],ha,wp.x); ffma2(acc2[2*p+1],ha,wp.y); }
            ffma2(acc2[16], ha, cW2p[(2*jh)*18 + 16]);
        }
        {
            u64 hb = packf2(softplus_fast(bb));
            const ulonglong2* w2 = reinterpret_cast<const ulonglong2*>(&cW2p[(2*jh+1)*18]);
            #pragma unroll
            for (int p=0;p<8;p++){ ulonglong2 wp = w2[p]; ffma2(acc2[2*p],hb,wp.x); ffma2(acc2[2*p+1],hb,wp.y); }
            ffma2(acc2[16], hb, cW2p[(2*jh+1)*18 + 16]);
        }
    }

    float ov[34];
    #pragma unroll
    for (int p=0;p<17;p++) unpack2(acc2[p], ov[2*p], ov[2*p+1]);
    g_sigma[base] = ov[0];
    float4* cdst = reinterpret_cast<float4*>(g_colors + (size_t)base*NCH);
    #pragma unroll
    for (int t=0;t<8;t++){
        float4 v;
        v.x = decode_rgb_fast(ov[1+4*t+0]);
        v.y = decode_rgb_fast(ov[1+4*t+1]);
        v.z = decode_rgb_fast(ov[1+4*t+2]);
        v.w = decode_rgb_fast(ov[1+4*t+3]);
        cdst[t] = v;
    }
}

// ---- fused coarse march + pdf smoothing + cdf (per-ray, weights stay in regs) ----
__global__ void k_cmarch_cdf(){
    int ray = blockIdx.x*blockDim.x + threadIdx.x;
    if (ray >= RR) return;
    const float* dep = g_depths + ray*STOT;
    const float* sig = g_sigma  + ray*STOT;
    float w[DD-1];
    float T = 1.f;
    float sp = sig[0], dp = dep[0];
    #pragma unroll 1
    for (int s=1; s<DD; s++){
        float sc = sig[s], dc = dep[s];
        float delta = dc - dp;
        float dm = softplusf(0.5f*(sp+sc) - 1.f);
        float alpha = 1.f - expf(-dm*delta);
        w[s-1] = alpha*T;
        T *= (1.f - alpha + 1e-10f);
        sp = sc; dp = dc;
    }
    float m[DD];
    m[0] = w[0]; m[DD-1] = w[DD-2];
    #pragma unroll 1
    for (int i=1;i<DD-1;i++) m[i] = fmaxf(w[i-1], w[i]);
    float pw[MIMP]; float tot = 0.f;
    #pragma unroll 1
    for (int i=0;i<MIMP;i++){
        pw[i] = 0.5f*(m[i+1] + m[i+2]) + 0.01f + 1e-5f;
        tot += pw[i];
    }
    float* cdf = g_cdf + ray*(MIMP+1);
    cdf[0] = 0.f;
    float run = 0.f;
    #pragma unroll 1
    for (int i=0;i<MIMP;i++){ run += pw[i]/tot; cdf[i+1] = run; }
}

// per-sample: searchsorted-right (upper_bound) + interp; folds fine-depth minmax
__global__ void k_sample(const float* __restrict__ u){
    int idx = blockIdx.x*blockDim.x + threadIdx.x;
    if (idx >= RR*NIMP) return;
    int ray = idx / NIMP, t = idx - ray*NIMP;
    float uu = u[idx];
    const float* cdf = g_cdf + ray*(MIMP+1);
    int lo = 0, hi = MIMP+1;           // first index with cdf[i] > u
    while (lo < hi){
        int mid = (lo + hi) >> 1;
        if (cdf[mid] <= uu) lo = mid + 1; else hi = mid;
    }
    int ind = lo;
    int below = max(ind-1, 0);
    int above = min(ind, MIMP);
    float cb = cdf[below], ca = cdf[above];
    const float* z = g_depths + ray*STOT;
    float bb = z[below], ba = z[above];
    float denom = ca - cb;
    if (denom < 1e-5f) denom = 1.f;
    float zf = bb + (uu - cb)/denom*(ba - bb);
    g_depths[ray*STOT + DD + t] = zf;
    warp_minmax_atomic(zf);
}

// ---- fused order + final march + rgb: one block (96 threads) per ray ----
__global__ void __launch_bounds__(96) k_final(float* __restrict__ out){
    __shared__ float sd[STOT];
    __shared__ float ss[STOT];
    __shared__ unsigned char sord[STOT];
    __shared__ float sw[STOT-1];
    int ray = blockIdx.x;
    int tid = threadIdx.x;

    sd[tid] = g_depths[ray*STOT + tid];
    ss[tid] = g_sigma[ray*STOT + tid];
    __syncthreads();

    // parallel stable-merge rank (exact stable argsort semantics)
    {
        int i = tid, pos;
        if (i < DD){
            float z = sd[i];
            int cnt = 0;
            #pragma unroll 1
            for (int j=0;j<NIMP;j++) cnt += (sd[DD+j] < z) ? 1 : 0;
            pos = i + cnt;
        } else {
            int t = i - DD;
            float z = sd[i];
            int cc = 0;
            #pragma unroll 1
            for (int s=0;s<DD;s++) cc += (sd[s] <= z) ? 1 : 0;
            int cf = 0;
            #pragma unroll 1
            for (int j=0;j<NIMP;j++){
                float zj = sd[DD+j];
                cf += (zj < z || (zj == z && j < t)) ? 1 : 0;
            }
            pos = cc + cf;
        }
        sord[pos] = (unsigned char)i;
    }
    __syncthreads();

    // serial march on lane 0 (weights -> smem)
    if (tid == 0){
        float T = 1.f, wtot = 0.f, dsum = 0.f;
        int ip = sord[0];
        float dprev = sd[ip], sp = ss[ip];
        #pragma unroll 1
        for (int s=1;s<STOT;s++){
            int ic = sord[s];
            float dc = sd[ic], sc = ss[ic];
            float delta = dc - dprev;
            float dm = softplusf(0.5f*(sp+sc) - 1.f);
            float alpha = 1.f - expf(-dm*delta);
            float wgt = alpha*T;
            sw[s-1] = wgt;
            wtot += wgt;
            dsum += wgt*0.5f*(dprev + dc);
            T *= (1.f - alpha + 1e-10f);
            dprev = dc; sp = sc;
        }
        float depth = dsum/wtot;
        if (isnan(depth)) depth = __int_as_float(0x7f800000);
        float dmin = __uint_as_float(g_dmin_bits), dmax = __uint_as_float(g_dmax_bits);
        depth = fminf(fmaxf(depth, dmin), dmax);
        out[ray*34 + 32] = depth;
        out[ray*34 + 33] = wtot;
    }
    __syncthreads();

    // rgb: lanes 0..31, one channel each; coalesced 128B color rows
    if (tid < NCH){
        int c = tid;
        const float* col = g_colors + (size_t)ray*STOT*NCH;
        float acc = 0.f;
        float cp = col[(int)sord[0]*NCH + c];
        #pragma unroll 1
        for (int s=1;s<STOT;s++){
            float cc = col[(int)sord[s]*NCH + c];
            acc = fmaf(sw[s-1]*0.5f, cp + cc, acc);
            cp = cc;
        }
        out[ray*34 + c] = acc*2.f - 1.f;
    }
}

extern "C" void kernel_launch(void* const* d_in, const int* in_sizes, int n_in,
                              void* d_out, int out_size){
    const float* planes = (const float*)d_in[0];
    const float* ro     = (const float*)d_in[1];
    const float* rd     = (const float*)d_in[2];
    const float* noise  = (const float*)d_in[3];
    const float* pdfu   = (const float*)d_in[4];
    const float* W2g    = (const float*)d_in[7];
    const float* B2g    = (const float*)d_in[8];
    float* out = (float*)d_out;

    cudaMemcpyToSymbolAsync(cW1f, d_in[5], FD*HID*sizeof(float), 0, cudaMemcpyDeviceToDevice, 0);
    cudaMemcpyToSymbolAsync(cB1f, d_in[6], HID*sizeof(float),    0, cudaMemcpyDeviceToDevice, 0);

    // pack W2/B2 on device, then stage into constant memory
    k_prepW2<<<(HID*18 + 127)/128, 128>>>(W2g, B2g);
    {
        void* pW2 = nullptr; void* pB2 = nullptr;
        cudaGetSymbolAddress(&pW2, g_W2p);
        cudaGetSymbolAddress(&pB2, g_B2p);
        cudaMemcpyToSymbolAsync(cW2p, pW2, HID*18*sizeof(u64), 0, cudaMemcpyDeviceToDevice, 0);
        cudaMemcpyToSymbolAsync(cB2p, pB2, 17*sizeof(u64),     0, cudaMemcpyDeviceToDevice, 0);
    }

    k_poses<<<1, 32>>>();
    k_transpose<<<(BB*NPL*HH*HH + 255)/256, 256>>>(planes);
    k_depths<<<(RR*DD + 255)/256, 256>>>(noise);

    // coarse pass
    k_pass<<<(RR*DD)/128, 128>>>(ro, rd, 0);
    k_cmarch_cdf<<<(RR + 63)/64, 64>>>();
    k_sample<<<(RR*NIMP + 255)/256, 256>>>(pdfu);

    // fine pass (NIMP == DD so the same index math applies)
    k_pass<<<(RR*NIMP)/128, 128>>>(ro, rd, DD);

    // fused order + final march + rgb
    k_final<<<RR, 96>>>(out);
}

// round 15
// speedup vs baseline: 1.1036x; 1.0189x over previous
#include <cuda_runtime.h>
#include <math.h>

// ---- fixed problem dims (setup_inputs) ----
#define BB   2
#define NN   4096
#define RR   (BB*NN)        // 8192 rays
#define HH   64             // plane H = W
#define DD   48             // coarse samples
#define NIMP 48             // importance samples
#define STOT (DD+NIMP)      // 96
#define NPL  32             // planes
#define NCH  32             // rgb channels
#define FD   160            // feature dim
#define HID  64
#define OD   33
#define MIMP (DD-3)         // 45 pdf bins
#define PI_D 3.14159265358979323846

typedef unsigned long long u64;

// ---- scratch (device globals: no allocations allowed) ----
__device__ float g_poses[NPL*12];
__device__ float g_planesP[BB*NPL*HH*HH*4];   // [B,32,H,W] float4 texels (plane-major)
__device__ float g_depths[RR*STOT];
__device__ float g_sigma[RR*STOT];
__device__ float g_colors[RR*STOT*NCH];
__device__ float g_wf[RR*(STOT-1)];
__device__ float g_cdf[RR*(MIMP+1)];
__device__ float g_ac[RR*(DD-1)];             // coarse per-segment alpha
__device__ float2 g_am[RR*(STOT-1)];          // final per-segment (alpha, zmid)
__device__ unsigned char g_sidx[RR*STOT];     // merged order
__device__ unsigned int g_dmin_bits;
__device__ unsigned int g_dmax_bits;
__device__ __align__(16) u64 g_W2p[HID*18];
__device__ __align__(16) u64 g_B2p[17];

// MLP weights: warp-uniform reads -> constant/uniform port, off L1
__constant__ __align__(16) float cW1f[FD*HID];   // 40KB
__constant__ __align__(16) float cB1f[HID];
__constant__ __align__(16) u64   cW2p[HID*18];   // 9KB
__constant__ __align__(16) u64   cB2p[17];

__device__ __forceinline__ float softplusf(float x){          // precise (tail kernels)
    return fmaxf(x, 0.f) + log1pf(expf(-fabsf(x)));
}
__device__ __forceinline__ float softplus_fast(float x){      // k_pass
    return fmaxf(x, 0.f) + __logf(1.f + __expf(-fabsf(x)));
}
__device__ __forceinline__ float decode_rgb_fast(float a){
    return __fdividef(1.002f, 1.f + __expf(-a)) - 0.001f;
}

__device__ __forceinline__ void ffma2(u64& acc, u64 ab, u64 w){
    asm("fma.rn.f32x2 %0, %1, %2, %0;" : "+l"(acc) : "l"(ab), "l"(w));
}
__device__ __forceinline__ u64 packf2(float f){
    u64 r; asm("mov.b64 %0, {%1, %1};" : "=l"(r) : "f"(f)); return r;
}
__device__ __forceinline__ u64 pack2(float a, float b){
    u64 r; asm("mov.b64 %0, {%1, %2};" : "=l"(r) : "f"(a), "f"(b)); return r;
}
__device__ __forceinline__ void unpack2(u64 v, float& a, float& b){
    asm("mov.b64 {%0, %1}, %2;" : "=f"(a), "=f"(b) : "l"(v));
}

__device__ __forceinline__ void warp_minmax_atomic(float v){
    unsigned lo = __float_as_uint(v), hi = lo;   // depths > 0: uint order == float order
    #pragma unroll
    for (int o=16;o;o>>=1){
        lo = min(lo, __shfl_xor_sync(0xffffffffu, lo, o));
        hi = max(hi, __shfl_xor_sync(0xffffffffu, hi, o));
    }
    if ((threadIdx.x & 31) == 0){ atomicMin(&g_dmin_bits, lo); atomicMax(&g_dmax_bits, hi); }
}

__device__ void mm4(const double* A, const double* B, double* C){
    #pragma unroll
    for (int r=0;r<4;r++)
    #pragma unroll
    for (int c=0;c<4;c++){
        double s=0.0;
        #pragma unroll
        for (int k=0;k<4;k++) s += A[r*4+k]*B[k*4+c];
        C[r*4+c]=s;
    }
}

// ---- camera pose constants, computed in double to match numpy ----
__global__ void k_poses(){
    int i = threadIdx.x;
    if (i == 0){ g_dmin_bits = 0x7f800000u; g_dmax_bits = 0u; }
    if (i >= NPL) return;
    double y  = 1.0 - (i/31.0)*2.0;
    double r  = sqrt(1.0 - y*y);
    double golden = PI_D * (sqrt(5.0) - 1.0);
    double th = golden * (double)i;
    double x  = cos(th)*r, z = sin(th)*r;
    double phi   = atan2(z, sqrt(x*x + y*y));
    double theta = atan2(y, x);
    double radius = -1.307;
    double p = phi/180.0*PI_D;
    double t = theta/180.0*PI_D;
    double e = 90.0/180.0*PI_D;

    double Tm[16]={1,0,0,0, 0,1,0,0, 0,0,1,radius, 0,0,0,1};
    double Pm[16]={1,0,0,0, 0,cos(p),-sin(p),0, 0,sin(p),cos(p),0, 0,0,0,1};
    double Th[16]={cos(t),0,-sin(t),0, 0,1,0,0, sin(t),0,cos(t),0, 0,0,0,1};
    double Em[16]={cos(e),sin(e),0,0, -sin(e),cos(e),0,0, 0,0,1,0, 0,0,0,1};
    double Fm[16]={-1,0,0,0, 0,0,1,0, 0,1,0,0, 0,0,0,1};
    double t1[16], t2[16];
    mm4(Pm,Tm,t1); mm4(Th,t1,t2); mm4(Em,t2,t1); mm4(Fm,t1,t2);   // t2 = c2w
    double A[16];
    #pragma unroll
    for (int rr=0;rr<4;rr++){
        A[rr*4+0] = -t2[rr*4+0];
        A[rr*4+1] =  t2[rr*4+1];
        A[rr*4+2] =  t2[rr*4+2];
        A[rr*4+3] =  t2[rr*4+3];
    }
    #pragma unroll
    for (int rr=0;rr<3;rr++){
        g_poses[i*12 + rr*4 + 0] = (float)A[0*4+rr];
        g_poses[i*12 + rr*4 + 1] = (float)A[1*4+rr];
        g_poses[i*12 + rr*4 + 2] = (float)A[2*4+rr];
        double tr = -(A[0*4+rr]*A[0*4+3] + A[1*4+rr]*A[1*4+3] + A[2*4+rr]*A[2*4+3]);
        g_poses[i*12 + rr*4 + 3] = (float)tr;
    }
}

// ---- pack W2/B2 into padded u64 pair tables (staged, then copied to constant) ----
__global__ void k_prepW2(const float* __restrict__ W2g, const float* __restrict__ B2g){
    int i = blockIdx.x*blockDim.x + threadIdx.x;
    if (i < HID*18){
        int j = i/18, p = i - j*18;
        float lo = (p < 17) ? W2g[j*OD + 2*p] : 0.f;
        float hi = (p < 16) ? W2g[j*OD + 2*p+1] : 0.f;
        g_W2p[i] = pack2(lo, hi);
    }
    if (i < 17) g_B2p[i] = pack2(B2g[2*i], (i<16)? B2g[2*i+1] : 0.f);
}

// ---- planes [B,96,H,W] -> [B,32,H,W] float4 (plane-major texels) ----
__global__ void k_transpose(const float* __restrict__ planes){
    int i = blockIdx.x*blockDim.x + threadIdx.x;
    if (i >= BB*NPL*HH*HH) return;
    int x  = i & 63; int t = i >> 6;
    int yy = t & 63; t >>= 6;
    int kk = t & 31; int b = t >> 5;
    float4 v;
    v.x = planes[((b*96 + 3*kk+0)*HH + yy)*HH + x];
    v.y = planes[((b*96 + 3*kk+1)*HH + yy)*HH + x];
    v.z = planes[((b*96 + 3*kk+2)*HH + yy)*HH + x];
    v.w = 0.f;
    reinterpret_cast<float4*>(g_planesP)[i] = v;
}

__global__ void k_depths(const float* __restrict__ noise){
    int i = blockIdx.x*blockDim.x + threadIdx.x;
    if (i >= RR*DD) return;
    int s = i % DD; int ray = i / DD;
    const float step = (2.5f - 0.5f)/(float)(DD-1);
    float d = 0.5f + (float)s*step + noise[i]*step;
    g_depths[ray*STOT + s] = d;
    warp_minmax_atomic(d);
}

// ---- fused feature gather + MLP: one lane = one point (R12 body, unchanged) ----
__global__ void __launch_bounds__(128, 4) k_pass(const float* __restrict__ ro,
                                                 const float* __restrict__ rd,
                                                 int scol0){
    __shared__ __align__(16) float sPoses[NPL*12];
    int tid = threadIdx.x;
    for (int i = tid; i < NPL*12; i += 128) sPoses[i] = g_poses[i];
    __syncthreads();

    int q = blockIdx.x*128 + tid;                 // point index, samples fastest
    int b   = q / (NN*DD);
    int rem = q - b*(NN*DD);
    int n   = rem / DD;
    int s   = rem - n*DD;
    int ray = b*NN + n;
    int base = ray*STOT + scol0 + s;

    float depth = g_depths[base];
    float ox = ro[ray*3+0], oy = ro[ray*3+1], oz = ro[ray*3+2];
    float dx = rd[ray*3+0], dy = rd[ray*3+1], dz = rd[ray*3+2];
    float px = fmaf(depth,dx,ox), py = fmaf(depth,dy,oy), pz = fmaf(depth,dz,oz);
    const float4* planeB = reinterpret_cast<const float4*>(g_planesP) + b*(NPL*HH*HH);

    u64 acc[32];
    {
        const ulonglong2* b2 = reinterpret_cast<const ulonglong2*>(cB1f);
        #pragma unroll
        for (int p=0;p<16;p++){ ulonglong2 bp = b2[p]; acc[2*p] = bp.x; acc[2*p+1] = bp.y; }
    }

    #pragma unroll 1
    for (int kk=0; kk<NPL; kk++){
        const float* P = sPoses + kk*12;
        float cx = fmaf(P[0],px, fmaf(P[1],py, fmaf(P[2],pz,  P[3])));
        float cy = fmaf(P[4],px, fmaf(P[5],py, fmaf(P[6],pz,  P[7])));
        float cz = fmaf(P[8],px, fmaf(P[9],py, fmaf(P[10],pz, P[11])));
        float gx = fminf(fmaxf((1.0254f*cx + 0.5f*cz)/cz, 0.f), 1.f)*2.f - 1.f;
        float gy = fminf(fmaxf((1.0254f*cy + 0.5f*cz)/cz, 0.f), 1.f)*2.f - 1.f;
        float ix = ((gx + 1.f)*(float)HH - 1.f)*0.5f;
        float iy = ((gy + 1.f)*(float)HH - 1.f)*0.5f;
        float x0 = floorf(ix), y0 = floorf(iy);
        float wx = ix - x0,    wy = iy - y0;
        float vx0 = (x0 >= 0.f)  ? 1.f : 0.f;
        float vx1 = (x0 <= 62.f) ? 1.f : 0.f;
        float vy0 = (y0 >= 0.f)  ? 1.f : 0.f;
        float vy1 = (y0 <= 62.f) ? 1.f : 0.f;
        int x0i = (int)x0, y0i = (int)y0;
        int x0c = max(x0i, 0),   y0c = max(y0i, 0);
        int x1c = min(x0i+1,63), y1c = min(y0i+1,63);
        float w00 = (1.f-wx)*(1.f-wy)*vx0*vy0;
        float w10 = wx*(1.f-wy)*vx1*vy0;
        float w01 = (1.f-wx)*wy*vx0*vy1;
        float w11 = wx*wy*vx1*vy1;
        const float4* planeK = planeB + kk*(HH*HH);
        float4 t00 = planeK[y0c*HH + x0c];
        float4 t10 = planeK[y0c*HH + x1c];
        float4 t01 = planeK[y1c*HH + x0c];
        float4 t11 = planeK[y1c*HH + x1c];

        {
            u64 ff = packf2(gx);
            const ulonglong2* w2 = reinterpret_cast<const ulonglong2*>(&cW1f[(96+2*kk)*HID]);
            #pragma unroll
            for (int p=0;p<16;p++){ ulonglong2 wp = w2[p]; ffma2(acc[2*p],ff,wp.x); ffma2(acc[2*p+1],ff,wp.y); }
        }
        {
            u64 ff = packf2(gy);
            const ulonglong2* w2 = reinterpret_cast<const ulonglong2*>(&cW1f[(96+2*kk+1)*HID]);
            #pragma unroll
            for (int p=0;p<16;p++){ ulonglong2 wp = w2[p]; ffma2(acc[2*p],ff,wp.x); ffma2(acc[2*p+1],ff,wp.y); }
        }
        float c0 = t00.x*w00 + t10.x*w10 + t01.x*w01 + t11.x*w11;
        float c1 = t00.y*w00 + t10.y*w10 + t01.y*w01 + t11.y*w11;
        float c2 = t00.z*w00 + t10.z*w10 + t01.z*w01 + t11.z*w11;
        {
            u64 ff = packf2(c0);
            const ulonglong2* w2 = reinterpret_cast<const ulonglong2*>(&cW1f[(3*kk+0)*HID]);
            #pragma unroll
            for (int p=0;p<16;p++){ ulonglong2 wp = w2[p]; ffma2(acc[2*p],ff,wp.x); ffma2(acc[2*p+1],ff,wp.y); }
        }
        {
            u64 ff = packf2(c1);
            const ulonglong2* w2 = reinterpret_cast<const ulonglong2*>(&cW1f[(3*kk+1)*HID]);
            #pragma unroll
            for (int p=0;p<16;p++){ ulonglong2 wp = w2[p]; ffma2(acc[2*p],ff,wp.x); ffma2(acc[2*p+1],ff,wp.y); }
        }
        {
            u64 ff = packf2(c2);
            const ulonglong2* w2 = reinterpret_cast<const ulonglong2*>(&cW1f[(3*kk+2)*HID]);
            #pragma unroll
            for (int p=0;p<16;p++){ ulonglong2 wp = w2[p]; ffma2(acc[2*p],ff,wp.x); ffma2(acc[2*p+1],ff,wp.y); }
        }
    }

    // layer 2 + decode, fully in registers (W2 via constant port)
    u64 acc2[17];
    #pragma unroll
    for (int p=0;p<17;p++) acc2[p] = cB2p[p];
    #pragma unroll
    for (int jh=0; jh<32; jh++){
        float a, bb;
        unpack2(acc[jh], a, bb);
        {
            u64 ha = packf2(softplus_fast(a));
            const ulonglong2* w2 = reinterpret_cast<const ulonglong2*>(&cW2p[(2*jh)*18]);
            #pragma unroll
            for (int p=0;p<8;p++){ ulonglong2 wp = w2[p]; ffma2(acc2[2*p],ha,wp.x); ffma2(acc2[2*p+1],ha,wp.y); }
            ffma2(acc2[16], ha, cW2p[(2*jh)*18 + 16]);
        }
        {
            u64 hb = packf2(softplus_fast(bb));
            const ulonglong2* w2 = reinterpret_cast<const ulonglong2*>(&cW2p[(2*jh+1)*18]);
            #pragma unroll
            for (int p=0;p<8;p++){ ulonglong2 wp = w2[p]; ffma2(acc2[2*p],hb,wp.x); ffma2(acc2[2*p+1],hb,wp.y); }
            ffma2(acc2[16], hb, cW2p[(2*jh+1)*18 + 16]);
        }
    }

    float ov[34];
    #pragma unroll
    for (int p=0;p<17;p++) unpack2(acc2[p], ov[2*p], ov[2*p+1]);
    g_sigma[base] = ov[0];
    float4* cdst = reinterpret_cast<float4*>(g_colors + (size_t)base*NCH);
    #pragma unroll
    for (int t=0;t<8;t++){
        float4 v;
        v.x = decode_rgb_fast(ov[1+4*t+0]);
        v.y = decode_rgb_fast(ov[1+4*t+1]);
        v.z = decode_rgb_fast(ov[1+4*t+2]);
        v.w = decode_rgb_fast(ov[1+4*t+3]);
        cdst[t] = v;
    }
}

// ---- coarse per-segment alpha (flat parallel, hides transcendental latency) ----
__global__ void k_alphac(){
    int idx = blockIdx.x*blockDim.x + threadIdx.x;
    if (idx >= RR*(DD-1)) return;
    int ray = idx / (DD-1), s = idx - ray*(DD-1);
    const float* dep = g_depths + ray*STOT;
    const float* sig = g_sigma  + ray*STOT;
    float delta = dep[s+1] - dep[s];
    float dm = softplusf(0.5f*(sig[s] + sig[s+1]) - 1.f);
    g_ac[idx] = 1.f - expf(-dm*delta);
}

// ---- per-ray cheap scan: weights -> smoothed pdf -> cdf ----
__global__ void k_cdf(){
    int ray = blockIdx.x*blockDim.x + threadIdx.x;
    if (ray >= RR) return;
    const float* ac = g_ac + ray*(DD-1);
    float w[DD-1];
    float T = 1.f;
    #pragma unroll 1
    for (int s=0; s<DD-1; s++){
        float a = ac[s];
        w[s] = a*T;
        T *= (1.f - a + 1e-10f);
    }
    float m[DD];
    m[0] = w[0]; m[DD-1] = w[DD-2];
    #pragma unroll 1
    for (int i=1;i<DD-1;i++) m[i] = fmaxf(w[i-1], w[i]);
    float pw[MIMP]; float tot = 0.f;
    #pragma unroll 1
    for (int i=0;i<MIMP;i++){
        pw[i] = 0.5f*(m[i+1] + m[i+2]) + 0.01f + 1e-5f;
        tot += pw[i];
    }
    float* cdf = g_cdf + ray*(MIMP+1);
    cdf[0] = 0.f;
    float run = 0.f;
    #pragma unroll 1
    for (int i=0;i<MIMP;i++){ run += pw[i]/tot; cdf[i+1] = run; }
}

// per-sample: searchsorted-right (upper_bound) + interp; folds fine-depth minmax
__global__ void k_sample(const float* __restrict__ u){
    int idx = blockIdx.x*blockDim.x + threadIdx.x;
    if (idx >= RR*NIMP) return;
    int ray = idx / NIMP, t = idx - ray*NIMP;
    float uu = u[idx];
    const float* cdf = g_cdf + ray*(MIMP+1);
    int lo = 0, hi = MIMP+1;           // first index with cdf[i] > u
    while (lo < hi){
        int mid = (lo + hi) >> 1;
        if (cdf[mid] <= uu) lo = mid + 1; else hi = mid;
    }
    int ind = lo;
    int below = max(ind-1, 0);
    int above = min(ind, MIMP);
    float cb = cdf[below], ca = cdf[above];
    const float* z = g_depths + ray*STOT;
    float bb = z[below], ba = z[above];
    float denom = ca - cb;
    if (denom < 1e-5f) denom = 1.f;
    float zf = bb + (uu - cb)/denom*(ba - bb);
    g_depths[ray*STOT + DD + t] = zf;
    warp_minmax_atomic(zf);
}

// ---- parallel stable-merge order: one thread per (ray, sample) ----
__global__ void k_order(){
    int idx = blockIdx.x*blockDim.x + threadIdx.x;
    if (idx >= RR*STOT) return;
    int ray = idx / STOT, i = idx - ray*STOT;
    const float* dep = g_depths + ray*STOT;
    int pos;
    if (i < DD){
        float z = dep[i];
        int cnt = 0;
        #pragma unroll 1
        for (int j=0;j<NIMP;j++) cnt += (dep[DD+j] < z) ? 1 : 0;
        pos = i + cnt;
    } else {
        int t = i - DD;
        float z = dep[i];
        int cc = 0;
        #pragma unroll 1
        for (int s=0;s<DD;s++) cc += (dep[s] <= z) ? 1 : 0;
        int cf = 0;
        #pragma unroll 1
        for (int j=0;j<NIMP;j++){
            float zj = dep[DD+j];
            cf += (zj < z || (zj == z && j < t)) ? 1 : 0;
        }
        pos = cc + cf;
    }
    g_sidx[ray*STOT + pos] = (unsigned char)i;
}

// ---- final per-segment alpha + midpoint (flat parallel) ----
__global__ void k_alphaf(){
    int idx = blockIdx.x*blockDim.x + threadIdx.x;
    if (idx >= RR*(STOT-1)) return;
    int ray = idx / (STOT-1), s = idx - ray*(STOT-1);
    const unsigned char* ord = g_sidx + ray*STOT;
    const float* dep = g_depths + ray*STOT;
    const float* sig = g_sigma  + ray*STOT;
    int i0 = ord[s], i1 = ord[s+1];
    float d0 = dep[i0], d1 = dep[i1];
    float dm = softplusf(0.5f*(sig[i0] + sig[i1]) - 1.f);
    float alpha = 1.f - expf(-dm*(d1 - d0));
    g_am[idx] = make_float2(alpha, 0.5f*(d0 + d1));
}

// ---- final march: cheap per-ray scan (FMA only) ----
__global__ void k_march(float* __restrict__ out){
    int ray = blockIdx.x*blockDim.x + threadIdx.x;
    if (ray >= RR) return;
    const float2* am = g_am + ray*(STOT-1);
    float* wf = g_wf + ray*(STOT-1);
    float T = 1.f, wtot = 0.f, dsum = 0.f;
    #pragma unroll 1
    for (int s=0;s<STOT-1;s++){
        float2 a = am[s];
        float wgt = a.x*T;
        wf[s] = wgt;
        wtot += wgt;
        dsum = fmaf(wgt, a.y, dsum);
        T *= (1.f - a.x + 1e-10f);
    }
    float depth = dsum/wtot;
    if (isnan(depth)) depth = __int_as_float(0x7f800000);
    float dmin = __uint_as_float(g_dmin_bits), dmax = __uint_as_float(g_dmax_bits);
    depth = fminf(fmaxf(depth, dmin), dmax);
    out[ray*34 + 32] = depth;
    out[ray*34 + 33] = wtot;
}

// channel-vectorized rgb: one thread = 4 channels of one ray
__global__ void k_rgb(float* __restrict__ out){
    int idx = blockIdx.x*blockDim.x + threadIdx.x;
    if (idx >= RR*8) return;
    int c4 = (idx & 7); int ray = idx >> 3;
    const unsigned char* mi = g_sidx + ray*STOT;
    const float4* col = reinterpret_cast<const float4*>(g_colors + (size_t)ray*STOT*NCH);
    const float* wv  = g_wf + ray*(STOT-1);
    float4 acc = make_float4(0.f,0.f,0.f,0.f);
    float4 cp = col[(int)mi[0]*8 + c4];
    #pragma unroll 1
    for (int s=1;s<STOT;s++){
        float4 cc = col[(int)mi[s]*8 + c4];
        float w = wv[s-1]*0.5f;
        acc.x += w*(cp.x + cc.x);
        acc.y += w*(cp.y + cc.y);
        acc.z += w*(cp.z + cc.z);
        acc.w += w*(cp.w + cc.w);
        cp = cc;
    }
    float* o = out + ray*34 + c4*4;
    o[0] = acc.x*2.f - 1.f;
    o[1] = acc.y*2.f - 1.f;
    o[2] = acc.z*2.f - 1.f;
    o[3] = acc.w*2.f - 1.f;
}

extern "C" void kernel_launch(void* const* d_in, const int* in_sizes, int n_in,
                              void* d_out, int out_size){
    const float* planes = (const float*)d_in[0];
    const float* ro     = (const float*)d_in[1];
    const float* rd     = (const float*)d_in[2];
    const float* noise  = (const float*)d_in[3];
    const float* pdfu   = (const float*)d_in[4];
    const float* W2g    = (const float*)d_in[7];
    const float* B2g    = (const float*)d_in[8];
    float* out = (float*)d_out;

    cudaMemcpyToSymbolAsync(cW1f, d_in[5], FD*HID*sizeof(float), 0, cudaMemcpyDeviceToDevice, 0);
    cudaMemcpyToSymbolAsync(cB1f, d_in[6], HID*sizeof(float),    0, cudaMemcpyDeviceToDevice, 0);

    // pack W2/B2 on device, then stage into constant memory
    k_prepW2<<<(HID*18 + 127)/128, 128>>>(W2g, B2g);
    {
        void* pW2 = nullptr; void* pB2 = nullptr;
        cudaGetSymbolAddress(&pW2, g_W2p);
        cudaGetSymbolAddress(&pB2, g_B2p);
        cudaMemcpyToSymbolAsync(cW2p, pW2, HID*18*sizeof(u64), 0, cudaMemcpyDeviceToDevice, 0);
        cudaMemcpyToSymbolAsync(cB2p, pB2, 17*sizeof(u64),     0, cudaMemcpyDeviceToDevice, 0);
    }

    k_poses<<<1, 32>>>();
    k_transpose<<<(BB*NPL*HH*HH + 255)/256, 256>>>(planes);
    k_depths<<<(RR*DD + 255)/256, 256>>>(noise);

    // coarse pass
    k_pass<<<(RR*DD)/128, 128>>>(ro, rd, 0);
    k_alphac<<<(RR*(DD-1) + 255)/256, 256>>>();
    k_cdf<<<(RR + 63)/64, 64>>>();
    k_sample<<<(RR*NIMP + 255)/256, 256>>>(pdfu);

    // fine pass (NIMP == DD so the same index math applies)
    k_pass<<<(RR*NIMP)/128, 128>>>(ro, rd, DD);

    // order + parallel alphas + cheap march + rgb
    k_order<<<(RR*STOT + 255)/256, 256>>>();
    k_alphaf<<<(RR*(STOT-1) + 255)/256, 256>>>();
    k_march<<<(RR + 63)/64, 64>>>(out);
    k_rgb<<<(RR*8 + 127)/128, 128>>>(out);
}

// round 16
// speedup vs baseline: 1.1348x; 1.0283x over previous
#include <cuda_runtime.h>
#include <math.h>

// ---- fixed problem dims (setup_inputs) ----
#define BB   2
#define NN   4096
#define RR   (BB*NN)        // 8192 rays
#define HH   64             // plane H = W
#define DD   48             // coarse samples
#define NIMP 48             // importance samples
#define STOT (DD+NIMP)      // 96
#define NPL  32             // planes
#define NCH  32             // rgb channels
#define FD   160            // feature dim
#define HID  64
#define OD   33
#define MIMP (DD-3)         // 45 pdf bins
#define PI_D 3.14159265358979323846

typedef unsigned long long u64;

// ---- scratch (device globals: no allocations allowed) ----
__device__ float g_poses[NPL*12];
__device__ float g_planesP[BB*NPL*HH*HH*4];   // [B,32,H,W] float4 texels (plane-major)
__device__ float g_depths[RR*STOT];
__device__ float g_sigma[RR*STOT];
__device__ float g_colors[RR*STOT*NCH];
__device__ float g_wf[RR*(STOT-1)];
__device__ float g_cdf[RR*(MIMP+1)];
__device__ unsigned char g_sidx[RR*STOT];     // merged order: g_sidx[ray*96+pos] = orig idx
__device__ unsigned int g_dmin_bits;
__device__ unsigned int g_dmax_bits;
__device__ __align__(16) u64 g_W2p[HID*18];   // packed W2 pairs (staging for constant)
__device__ __align__(16) u64 g_B2p[17];

// MLP weights: warp-uniform reads -> constant/uniform port, off L1
__constant__ __align__(16) float cW1f[FD*HID];   // 40KB
__constant__ __align__(16) float cB1f[HID];
__constant__ __align__(16) u64   cW2p[HID*18];   // 9KB
__constant__ __align__(16) u64   cB2p[17];

__device__ __forceinline__ float softplusf(float x){          // precise (tail kernels)
    return fmaxf(x, 0.f) + log1pf(expf(-fabsf(x)));
}
__device__ __forceinline__ float softplus_fast(float x){      // k_pass
    return fmaxf(x, 0.f) + __logf(1.f + __expf(-fabsf(x)));
}
__device__ __forceinline__ float decode_rgb_fast(float a){
    return __fdividef(1.002f, 1.f + __expf(-a)) - 0.001f;
}

__device__ __forceinline__ void ffma2(u64& acc, u64 ab, u64 w){
    asm("fma.rn.f32x2 %0, %1, %2, %0;" : "+l"(acc) : "l"(ab), "l"(w));
}
__device__ __forceinline__ u64 packf2(float f){
    u64 r; asm("mov.b64 %0, {%1, %1};" : "=l"(r) : "f"(f)); return r;
}
__device__ __forceinline__ u64 pack2(float a, float b){
    u64 r; asm("mov.b64 %0, {%1, %2};" : "=l"(r) : "f"(a), "f"(b)); return r;
}
__device__ __forceinline__ void unpack2(u64 v, float& a, float& b){
    asm("mov.b64 {%0, %1}, %2;" : "=f"(a), "=f"(b) : "l"(v));
}

__device__ __forceinline__ void warp_minmax_atomic(float v){
    unsigned lo = __float_as_uint(v), hi = lo;   // depths > 0: uint order == float order
    #pragma unroll
    for (int o=16;o;o>>=1){
        lo = min(lo, __shfl_xor_sync(0xffffffffu, lo, o));
        hi = max(hi, __shfl_xor_sync(0xffffffffu, hi, o));
    }
    if ((threadIdx.x & 31) == 0){ atomicMin(&g_dmin_bits, lo); atomicMax(&g_dmax_bits, hi); }
}

__device__ void mm4(const double* A, const double* B, double* C){
    #pragma unroll
    for (int r=0;r<4;r++)
    #pragma unroll
    for (int c=0;c<4;c++){
        double s=0.0;
        #pragma unroll
        for (int k=0;k<4;k++) s += A[r*4+k]*B[k*4+c];
        C[r*4+c]=s;
    }
}

// ---- camera pose constants, computed in double to match numpy ----
__global__ void k_poses(){
    int i = threadIdx.x;
    if (i == 0){ g_dmin_bits = 0x7f800000u; g_dmax_bits = 0u; }
    if (i >= NPL) return;
    double y  = 1.0 - (i/31.0)*2.0;
    double r  = sqrt(1.0 - y*y);
    double golden = PI_D * (sqrt(5.0) - 1.0);
    double th = golden * (double)i;
    double x  = cos(th)*r, z = sin(th)*r;
    double phi   = atan2(z, sqrt(x*x + y*y));
    double theta = atan2(y, x);
    double radius = -1.307;
    double p = phi/180.0*PI_D;
    double t = theta/180.0*PI_D;
    double e = 90.0/180.0*PI_D;

    double Tm[16]={1,0,0,0, 0,1,0,0, 0,0,1,radius, 0,0,0,1};
    double Pm[16]={1,0,0,0, 0,cos(p),-sin(p),0, 0,sin(p),cos(p),0, 0,0,0,1};
    double Th[16]={cos(t),0,-sin(t),0, 0,1,0,0, sin(t),0,cos(t),0, 0,0,0,1};
    double Em[16]={cos(e),sin(e),0,0, -sin(e),cos(e),0,0, 0,0,1,0, 0,0,0,1};
    double Fm[16]={-1,0,0,0, 0,0,1,0, 0,1,0,0, 0,0,0,1};
    double t1[16], t2[16];
    mm4(Pm,Tm,t1); mm4(Th,t1,t2); mm4(Em,t2,t1); mm4(Fm,t1,t2);   // t2 = c2w
    double A[16];
    #pragma unroll
    for (int rr=0;rr<4;rr++){
        A[rr*4+0] = -t2[rr*4+0];
        A[rr*4+1] =  t2[rr*4+1];
        A[rr*4+2] =  t2[rr*4+2];
        A[rr*4+3] =  t2[rr*4+3];
    }
    #pragma unroll
    for (int rr=0;rr<3;rr++){
        g_poses[i*12 + rr*4 + 0] = (float)A[0*4+rr];
        g_poses[i*12 + rr*4 + 1] = (float)A[1*4+rr];
        g_poses[i*12 + rr*4 + 2] = (float)A[2*4+rr];
        double tr = -(A[0*4+rr]*A[0*4+3] + A[1*4+rr]*A[1*4+3] + A[2*4+rr]*A[2*4+3]);
        g_poses[i*12 + rr*4 + 3] = (float)tr;
    }
}

// ---- pack W2/B2 into padded u64 pair tables (staged, then copied to constant) ----
__global__ void k_prepW2(const float* __restrict__ W2g, const float* __restrict__ B2g){
    int i = blockIdx.x*blockDim.x + threadIdx.x;
    if (i < HID*18){
        int j = i/18, p = i - j*18;
        float lo = (p < 17) ? W2g[j*OD + 2*p] : 0.f;
        float hi = (p < 16) ? W2g[j*OD + 2*p+1] : 0.f;
        g_W2p[i] = pack2(lo, hi);
    }
    if (i < 17) g_B2p[i] = pack2(B2g[2*i], (i<16)? B2g[2*i+1] : 0.f);
}

// ---- planes [B,96,H,W] -> [B,32,H,W] float4 (plane-major texels) ----
__global__ void k_transpose(const float* __restrict__ planes){
    int i = blockIdx.x*blockDim.x + threadIdx.x;
    if (i >= BB*NPL*HH*HH) return;
    int x  = i & 63; int t = i >> 6;
    int yy = t & 63; t >>= 6;
    int kk = t & 31; int b = t >> 5;
    float4 v;
    v.x = planes[((b*96 + 3*kk+0)*HH + yy)*HH + x];
    v.y = planes[((b*96 + 3*kk+1)*HH + yy)*HH + x];
    v.z = planes[((b*96 + 3*kk+2)*HH + yy)*HH + x];
    v.w = 0.f;
    reinterpret_cast<float4*>(g_planesP)[i] = v;
}

// ---- fused feature gather + MLP: one lane = one point (R12 body) ----
// coarse pass (scol0==0): computes depth from noise in-register, stores it,
// and does the global depth min/max (fine depths are convex combos of coarse
// bin edges, so the coarse range IS the global range).
__global__ void __launch_bounds__(128, 4) k_pass(const float* __restrict__ ro,
                                                 const float* __restrict__ rd,
                                                 const float* __restrict__ noise,
                                                 int scol0){
    __shared__ __align__(16) float sPoses[NPL*12];
    int tid = threadIdx.x;
    for (int i = tid; i < NPL*12; i += 128) sPoses[i] = g_poses[i];
    __syncthreads();

    int q = blockIdx.x*128 + tid;                 // point index, samples fastest
    int b   = q / (NN*DD);
    int rem = q - b*(NN*DD);
    int n   = rem / DD;
    int s   = rem - n*DD;
    int ray = b*NN + n;
    int base = ray*STOT + scol0 + s;

    float depth;
    if (scol0 == 0){
        const float step = (2.5f - 0.5f)/(float)(DD-1);
        depth = 0.5f + (float)s*step + noise[q]*step;
        g_depths[base] = depth;
        warp_minmax_atomic(depth);
    } else {
        depth = g_depths[base];
    }
    float ox = ro[ray*3+0], oy = ro[ray*3+1], oz = ro[ray*3+2];
    float dx = rd[ray*3+0], dy = rd[ray*3+1], dz = rd[ray*3+2];
    float px = fmaf(depth,dx,ox), py = fmaf(depth,dy,oy), pz = fmaf(depth,dz,oz);
    const float4* planeB = reinterpret_cast<const float4*>(g_planesP) + b*(NPL*HH*HH);

    u64 acc[32];
    {
        const ulonglong2* b2 = reinterpret_cast<const ulonglong2*>(cB1f);
        #pragma unroll
        for (int p=0;p<16;p++){ ulonglong2 bp = b2[p]; acc[2*p] = bp.x; acc[2*p+1] = bp.y; }
    }

    #pragma unroll 1
    for (int kk=0; kk<NPL; kk++){
        const float* P = sPoses + kk*12;
        float cx = fmaf(P[0],px, fmaf(P[1],py, fmaf(P[2],pz,  P[3])));
        float cy = fmaf(P[4],px, fmaf(P[5],py, fmaf(P[6],pz,  P[7])));
        float cz = fmaf(P[8],px, fmaf(P[9],py, fmaf(P[10],pz, P[11])));
        float gx = fminf(fmaxf((1.0254f*cx + 0.5f*cz)/cz, 0.f), 1.f)*2.f - 1.f;
        float gy = fminf(fmaxf((1.0254f*cy + 0.5f*cz)/cz, 0.f), 1.f)*2.f - 1.f;
        float ix = ((gx + 1.f)*(float)HH - 1.f)*0.5f;
        float iy = ((gy + 1.f)*(float)HH - 1.f)*0.5f;
        float x0 = floorf(ix), y0 = floorf(iy);
        float wx = ix - x0,    wy = iy - y0;
        float vx0 = (x0 >= 0.f)  ? 1.f : 0.f;
        float vx1 = (x0 <= 62.f) ? 1.f : 0.f;
        float vy0 = (y0 >= 0.f)  ? 1.f : 0.f;
        float vy1 = (y0 <= 62.f) ? 1.f : 0.f;
        int x0i = (int)x0, y0i = (int)y0;
        int x0c = max(x0i, 0),   y0c = max(y0i, 0);
        int x1c = min(x0i+1,63), y1c = min(y0i+1,63);
        float w00 = (1.f-wx)*(1.f-wy)*vx0*vy0;
        float w10 = wx*(1.f-wy)*vx1*vy0;
        float w01 = (1.f-wx)*wy*vx0*vy1;
        float w11 = wx*wy*vx1*vy1;
        const float4* planeK = planeB + kk*(HH*HH);
        float4 t00 = planeK[y0c*HH + x0c];
        float4 t10 = planeK[y0c*HH + x1c];
        float4 t01 = planeK[y1c*HH + x0c];
        float4 t11 = planeK[y1c*HH + x1c];

        {
            u64 ff = packf2(gx);
            const ulonglong2* w2 = reinterpret_cast<const ulonglong2*>(&cW1f[(96+2*kk)*HID]);
            #pragma unroll
            for (int p=0;p<16;p++){ ulonglong2 wp = w2[p]; ffma2(acc[2*p],ff,wp.x); ffma2(acc[2*p+1],ff,wp.y); }
        }
        {
            u64 ff = packf2(gy);
            const ulonglong2* w2 = reinterpret_cast<const ulonglong2*>(&cW1f[(96+2*kk+1)*HID]);
            #pragma unroll
            for (int p=0;p<16;p++){ ulonglong2 wp = w2[p]; ffma2(acc[2*p],ff,wp.x); ffma2(acc[2*p+1],ff,wp.y); }
        }
        float c0 = t00.x*w00 + t10.x*w10 + t01.x*w01 + t11.x*w11;
        float c1 = t00.y*w00 + t10.y*w10 + t01.y*w01 + t11.y*w11;
        float c2 = t00.z*w00 + t10.z*w10 + t01.z*w01 + t11.z*w11;
        {
            u64 ff = packf2(c0);
            const ulonglong2* w2 = reinterpret_cast<const ulonglong2*>(&cW1f[(3*kk+0)*HID]);
            #pragma unroll
            for (int p=0;p<16;p++){ ulonglong2 wp = w2[p]; ffma2(acc[2*p],ff,wp.x); ffma2(acc[2*p+1],ff,wp.y); }
        }
        {
            u64 ff = packf2(c1);
            const ulonglong2* w2 = reinterpret_cast<const ulonglong2*>(&cW1f[(3*kk+1)*HID]);
            #pragma unroll
            for (int p=0;p<16;p++){ ulonglong2 wp = w2[p]; ffma2(acc[2*p],ff,wp.x); ffma2(acc[2*p+1],ff,wp.y); }
        }
        {
            u64 ff = packf2(c2);
            const ulonglong2* w2 = reinterpret_cast<const ulonglong2*>(&cW1f[(3*kk+2)*HID]);
            #pragma unroll
            for (int p=0;p<16;p++){ ulonglong2 wp = w2[p]; ffma2(acc[2*p],ff,wp.x); ffma2(acc[2*p+1],ff,wp.y); }
        }
    }

    // layer 2 + decode, fully in registers (W2 via constant port)
    u64 acc2[17];
    #pragma unroll
    for (int p=0;p<17;p++) acc2[p] = cB2p[p];
    #pragma unroll
    for (int jh=0; jh<32; jh++){
        float a, bb;
        unpack2(acc[jh], a, bb);
        {
            u64 ha = packf2(softplus_fast(a));
            const ulonglong2* w2 = reinterpret_cast<const ulonglong2*>(&cW2p[(2*jh)*18]);
            #pragma unroll
            for (int p=0;p<8;p++){ ulonglong2 wp = w2[p]; ffma2(acc2[2*p],ha,wp.x); ffma2(acc2[2*p+1],ha,wp.y); }
            ffma2(acc2[16], ha, cW2p[(2*jh)*18 + 16]);
        }
        {
            u64 hb = packf2(softplus_fast(bb));
            const ulonglong2* w2 = reinterpret_cast<const ulonglong2*>(&cW2p[(2*jh+1)*18]);
            #pragma unroll
            for (int p=0;p<8;p++){ ulonglong2 wp = w2[p]; ffma2(acc2[2*p],hb,wp.x); ffma2(acc2[2*p+1],hb,wp.y); }
            ffma2(acc2[16], hb, cW2p[(2*jh+1)*18 + 16]);
        }
    }

    float ov[34];
    #pragma unroll
    for (int p=0;p<17;p++) unpack2(acc2[p], ov[2*p], ov[2*p+1]);
    g_sigma[base] = ov[0];
    float4* cdst = reinterpret_cast<float4*>(g_colors + (size_t)base*NCH);
    #pragma unroll
    for (int t=0;t<8;t++){
        float4 v;
        v.x = decode_rgb_fast(ov[1+4*t+0]);
        v.y = decode_rgb_fast(ov[1+4*t+1]);
        v.z = decode_rgb_fast(ov[1+4*t+2]);
        v.w = decode_rgb_fast(ov[1+4*t+3]);
        cdst[t] = v;
    }
}

// ---- fused coarse march + pdf smoothing + cdf (per-ray, weights stay in regs) ----
__global__ void k_cmarch_cdf(){
    int ray = blockIdx.x*blockDim.x + threadIdx.x;
    if (ray >= RR) return;
    const float* dep = g_depths + ray*STOT;
    const float* sig = g_sigma  + ray*STOT;
    float w[DD-1];
    float T = 1.f;
    float sp = sig[0], dp = dep[0];
    #pragma unroll 1
    for (int s=1; s<DD; s++){
        float sc = sig[s], dc = dep[s];
        float delta = dc - dp;
        float dm = softplusf(0.5f*(sp+sc) - 1.f);
        float alpha = 1.f - expf(-dm*delta);
        w[s-1] = alpha*T;
        T *= (1.f - alpha + 1e-10f);
        sp = sc; dp = dc;
    }
    float m[DD];
    m[0] = w[0]; m[DD-1] = w[DD-2];
    #pragma unroll 1
    for (int i=1;i<DD-1;i++) m[i] = fmaxf(w[i-1], w[i]);
    float pw[MIMP]; float tot = 0.f;
    #pragma unroll 1
    for (int i=0;i<MIMP;i++){
        pw[i] = 0.5f*(m[i+1] + m[i+2]) + 0.01f + 1e-5f;
        tot += pw[i];
    }
    float* cdf = g_cdf + ray*(MIMP+1);
    cdf[0] = 0.f;
    float run = 0.f;
    #pragma unroll 1
    for (int i=0;i<MIMP;i++){ run += pw[i]/tot; cdf[i+1] = run; }
}

// per-sample: searchsorted-right (upper_bound) + interp
// (no minmax here: fine depths are inside the coarse depth range by construction)
__global__ void k_sample(const float* __restrict__ u){
    int idx = blockIdx.x*blockDim.x + threadIdx.x;
    if (idx >= RR*NIMP) return;
    int ray = idx / NIMP, t = idx - ray*NIMP;
    float uu = u[idx];
    const float* cdf = g_cdf + ray*(MIMP+1);
    int lo = 0, hi = MIMP+1;           // first index with cdf[i] > u
    while (lo < hi){
        int mid = (lo + hi) >> 1;
        if (cdf[mid] <= uu) lo = mid + 1; else hi = mid;
    }
    int ind = lo;
    int below = max(ind-1, 0);
    int above = min(ind, MIMP);
    float cb = cdf[below], ca = cdf[above];
    const float* z = g_depths + ray*STOT;
    float bb = z[below], ba = z[above];
    float denom = ca - cb;
    if (denom < 1e-5f) denom = 1.f;
    g_depths[ray*STOT + DD + t] = bb + (uu - cb)/denom*(ba - bb);
}

// ---- parallel stable-merge order: one thread per (ray, sample) ----
__global__ void k_order(){
    int idx = blockIdx.x*blockDim.x + threadIdx.x;
    if (idx >= RR*STOT) return;
    int ray = idx / STOT, i = idx - ray*STOT;
    const float* dep = g_depths + ray*STOT;
    int pos;
    if (i < DD){
        float z = dep[i];
        int cnt = 0;
        #pragma unroll 1
        for (int j=0;j<NIMP;j++) cnt += (dep[DD+j] < z) ? 1 : 0;
        pos = i + cnt;
    } else {
        int t = i - DD;
        float z = dep[i];
        int cc = 0;
        #pragma unroll 1
        for (int s=0;s<DD;s++) cc += (dep[s] <= z) ? 1 : 0;
        int cf = 0;
        #pragma unroll 1
        for (int j=0;j<NIMP;j++){
            float zj = dep[DD+j];
            cf += (zj < z || (zj == z && j < t)) ? 1 : 0;
        }
        pos = cc + cf;
    }
    g_sidx[ray*STOT + pos] = (unsigned char)i;
}

// ---- final march over precomputed order ----
__global__ void k_march(float* __restrict__ out){
    int ray = blockIdx.x*blockDim.x + threadIdx.x;
    if (ray >= RR) return;
    const float* dep = g_depths + ray*STOT;
    const float* sig = g_sigma  + ray*STOT;
    const unsigned char* ord = g_sidx + ray*STOT;
    float T = 1.f, wtot = 0.f, dsum = 0.f;
    int ip = ord[0];
    float dprev = dep[ip], sp = sig[ip];
    #pragma unroll 1
    for (int s=1;s<STOT;s++){
        int ic = ord[s];
        float dc = dep[ic], sc = sig[ic];
        float delta = dc - dprev;
        float dm = softplusf(0.5f*(sp+sc) - 1.f);
        float alpha = 1.f - expf(-dm*delta);
        float wgt = alpha*T;
        g_wf[ray*(STOT-1) + s-1] = wgt;
        wtot += wgt;
        dsum += wgt*0.5f*(dprev + dc);
        T *= (1.f - alpha + 1e-10f);
        dprev = dc; sp = sc;
    }
    float depth = dsum/wtot;
    if (isnan(depth)) depth = __int_as_float(0x7f800000);
    float dmin = __uint_as_float(g_dmin_bits), dmax = __uint_as_float(g_dmax_bits);
    depth = fminf(fmaxf(depth, dmin), dmax);
    out[ray*34 + 32] = depth;
    out[ray*34 + 33] = wtot;
}

// channel-vectorized rgb: one thread = 4 channels of one ray
__global__ void k_rgb(float* __restrict__ out){
    int idx = blockIdx.x*blockDim.x + threadIdx.x;
    if (idx >= RR*8) return;
    int c4 = (idx & 7); int ray = idx >> 3;
    const unsigned char* mi = g_sidx + ray*STOT;
    const float4* col = reinterpret_cast<const float4*>(g_colors + (size_t)ray*STOT*NCH);
    const float* wv  = g_wf + ray*(STOT-1);
    float4 acc = make_float4(0.f,0.f,0.f,0.f);
    float4 cp = col[(int)mi[0]*8 + c4];
    #pragma unroll 1
    for (int s=1;s<STOT;s++){
        float4 cc = col[(int)mi[s]*8 + c4];
        float w = wv[s-1]*0.5f;
        acc.x += w*(cp.x + cc.x);
        acc.y += w*(cp.y + cc.y);
        acc.z += w*(cp.z + cc.z);
        acc.w += w*(cp.w + cc.w);
        cp = cc;
    }
    float* o = out + ray*34 + c4*4;
    o[0] = acc.x*2.f - 1.f;
    o[1] = acc.y*2.f - 1.f;
    o[2] = acc.z*2.f - 1.f;
    o[3] = acc.w*2.f - 1.f;
}

extern "C" void kernel_launch(void* const* d_in, const int* in_sizes, int n_in,
                              void* d_out, int out_size){
    const float* planes = (const float*)d_in[0];
    const float* ro     = (const float*)d_in[1];
    const float* rd     = (const float*)d_in[2];
    const float* noise  = (const float*)d_in[3];
    const float* pdfu   = (const float*)d_in[4];
    const float* W2g    = (const float*)d_in[7];
    const float* B2g    = (const float*)d_in[8];
    float* out = (float*)d_out;

    cudaMemcpyToSymbolAsync(cW1f, d_in[5], FD*HID*sizeof(float), 0, cudaMemcpyDeviceToDevice, 0);
    cudaMemcpyToSymbolAsync(cB1f, d_in[6], HID*sizeof(float),    0, cudaMemcpyDeviceToDevice, 0);

    // pack W2/B2 on device, then stage into constant memory
    k_prepW2<<<(HID*18 + 127)/128, 128>>>(W2g, B2g);
    {
        void* pW2 = nullptr; void* pB2 = nullptr;
        cudaGetSymbolAddress(&pW2, g_W2p);
        cudaGetSymbolAddress(&pB2, g_B2p);
        cudaMemcpyToSymbolAsync(cW2p, pW2, HID*18*sizeof(u64), 0, cudaMemcpyDeviceToDevice, 0);
        cudaMemcpyToSymbolAsync(cB2p, pB2, 17*sizeof(u64),     0, cudaMemcpyDeviceToDevice, 0);
    }

    k_poses<<<1, 32>>>();
    k_transpose<<<(BB*NPL*HH*HH + 255)/256, 256>>>(planes);

    // coarse pass (computes + stores coarse depths and the global depth range)
    k_pass<<<(RR*DD)/128, 128>>>(ro, rd, noise, 0);
    k_cmarch_cdf<<<(RR + 63)/64, 64>>>();
    k_sample<<<(RR*NIMP + 255)/256, 256>>>(pdfu);

    // fine pass (NIMP == DD so the same index math applies)
    k_pass<<<(RR*NIMP)/128, 128>>>(ro, rd, noise, DD);

    // merged order + final march + rgb
    k_order<<<(RR*STOT + 255)/256, 256>>>();
    k_march<<<(RR + 63)/64, 64>>>(out);
    k_rgb<<<(RR*8 + 127)/128, 128>>>(out);
}

// round 17
// speedup vs baseline: 1.1373x; 1.0022x over previous
#include <cuda_runtime.h>
#include <math.h>

// ---- fixed problem dims (setup_inputs) ----
#define BB   2
#define NN   4096
#define RR   (BB*NN)        // 8192 rays
#define HH   64             // plane H = W
#define DD   48             // coarse samples
#define NIMP 48             // importance samples
#define STOT (DD+NIMP)      // 96
#define NPL  32             // planes
#define NCH  32             // rgb channels
#define FD   160            // feature dim
#define HID  64
#define OD   33
#define MIMP (DD-3)         // 45 pdf bins
#define PI_D 3.14159265358979323846

typedef unsigned long long u64;

// ---- scratch (device globals: no allocations allowed) ----
__device__ float g_poses[NPL*12];
__device__ float g_planesP[BB*NPL*HH*HH*4];   // [B,32,H,W] float4 texels (plane-major)
__device__ float g_depths[RR*STOT];
__device__ float g_sigma[RR*STOT];
__device__ float g_colors[RR*STOT*NCH];
__device__ float g_wf[RR*(STOT-1)];
__device__ float g_cdf[RR*(MIMP+1)];
__device__ unsigned char g_sidx[RR*STOT];     // merged order: g_sidx[ray*96+pos] = orig idx
__device__ unsigned int g_dmin_bits;
__device__ unsigned int g_dmax_bits;
__device__ __align__(16) u64 g_W2p[HID*18];   // packed W2 pairs (staging for constant)
__device__ __align__(16) u64 g_B2p[17];

// MLP weights: warp-uniform reads -> constant/uniform port, off L1
__constant__ __align__(16) float cW1f[FD*HID];   // 40KB
__constant__ __align__(16) float cB1f[HID];
__constant__ __align__(16) u64   cW2p[HID*18];   // 9KB
__constant__ __align__(16) u64   cB2p[17];

__device__ __forceinline__ float softplusf(float x){          // precise (tail kernels)
    return fmaxf(x, 0.f) + log1pf(expf(-fabsf(x)));
}
__device__ __forceinline__ float softplus_fast(float x){      // k_pass
    return fmaxf(x, 0.f) + __logf(1.f + __expf(-fabsf(x)));
}
__device__ __forceinline__ float decode_rgb_fast(float a){
    return __fdividef(1.002f, 1.f + __expf(-a)) - 0.001f;
}

__device__ __forceinline__ void ffma2(u64& acc, u64 ab, u64 w){
    asm("fma.rn.f32x2 %0, %1, %2, %0;" : "+l"(acc) : "l"(ab), "l"(w));
}
__device__ __forceinline__ u64 packf2(float f){
    u64 r; asm("mov.b64 %0, {%1, %1};" : "=l"(r) : "f"(f)); return r;
}
__device__ __forceinline__ u64 pack2(float a, float b){
    u64 r; asm("mov.b64 %0, {%1, %2};" : "=l"(r) : "f"(a), "f"(b)); return r;
}
__device__ __forceinline__ void unpack2(u64 v, float& a, float& b){
    asm("mov.b64 {%0, %1}, %2;" : "=f"(a), "=f"(b) : "l"(v));
}

__device__ __forceinline__ void warp_minmax_atomic(float v){
    unsigned lo = __float_as_uint(v), hi = lo;   // depths > 0: uint order == float order
    #pragma unroll
    for (int o=16;o;o>>=1){
        lo = min(lo, __shfl_xor_sync(0xffffffffu, lo, o));
        hi = max(hi, __shfl_xor_sync(0xffffffffu, hi, o));
    }
    if ((threadIdx.x & 31) == 0){ atomicMin(&g_dmin_bits, lo); atomicMax(&g_dmax_bits, hi); }
}

__device__ void mm4(const double* A, const double* B, double* C){
    #pragma unroll
    for (int r=0;r<4;r++)
    #pragma unroll
    for (int c=0;c<4;c++){
        double s=0.0;
        #pragma unroll
        for (int k=0;k<4;k++) s += A[r*4+k]*B[k*4+c];
        C[r*4+c]=s;
    }
}

// ---- camera pose constants, computed in double to match numpy ----
__global__ void k_poses(){
    int i = threadIdx.x;
    if (i == 0){ g_dmin_bits = 0x7f800000u; g_dmax_bits = 0u; }
    if (i >= NPL) return;
    double y  = 1.0 - (i/31.0)*2.0;
    double r  = sqrt(1.0 - y*y);
    double golden = PI_D * (sqrt(5.0) - 1.0);
    double th = golden * (double)i;
    double x  = cos(th)*r, z = sin(th)*r;
    double phi   = atan2(z, sqrt(x*x + y*y));
    double theta = atan2(y, x);
    double radius = -1.307;
    double p = phi/180.0*PI_D;
    double t = theta/180.0*PI_D;
    double e = 90.0/180.0*PI_D;

    double Tm[16]={1,0,0,0, 0,1,0,0, 0,0,1,radius, 0,0,0,1};
    double Pm[16]={1,0,0,0, 0,cos(p),-sin(p),0, 0,sin(p),cos(p),0, 0,0,0,1};
    double Th[16]={cos(t),0,-sin(t),0, 0,1,0,0, sin(t),0,cos(t),0, 0,0,0,1};
    double Em[16]={cos(e),sin(e),0,0, -sin(e),cos(e),0,0, 0,0,1,0, 0,0,0,1};
    double Fm[16]={-1,0,0,0, 0,0,1,0, 0,1,0,0, 0,0,0,1};
    double t1[16], t2[16];
    mm4(Pm,Tm,t1); mm4(Th,t1,t2); mm4(Em,t2,t1); mm4(Fm,t1,t2);   // t2 = c2w
    double A[16];
    #pragma unroll
    for (int rr=0;rr<4;rr++){
        A[rr*4+0] = -t2[rr*4+0];
        A[rr*4+1] =  t2[rr*4+1];
        A[rr*4+2] =  t2[rr*4+2];
        A[rr*4+3] =  t2[rr*4+3];
    }
    #pragma unroll
    for (int rr=0;rr<3;rr++){
        g_poses[i*12 + rr*4 + 0] = (float)A[0*4+rr];
        g_poses[i*12 + rr*4 + 1] = (float)A[1*4+rr];
        g_poses[i*12 + rr*4 + 2] = (float)A[2*4+rr];
        double tr = -(A[0*4+rr]*A[0*4+3] + A[1*4+rr]*A[1*4+3] + A[2*4+rr]*A[2*4+3]);
        g_poses[i*12 + rr*4 + 3] = (float)tr;
    }
}

// ---- pack W2/B2 into padded u64 pair tables (staged, then copied to constant) ----
__global__ void k_prepW2(const float* __restrict__ W2g, const float* __restrict__ B2g){
    int i = blockIdx.x*blockDim.x + threadIdx.x;
    if (i < HID*18){
        int j = i/18, p = i - j*18;
        float lo = (p < 17) ? W2g[j*OD + 2*p] : 0.f;
        float hi = (p < 16) ? W2g[j*OD + 2*p+1] : 0.f;
        g_W2p[i] = pack2(lo, hi);
    }
    if (i < 17) g_B2p[i] = pack2(B2g[2*i], (i<16)? B2g[2*i+1] : 0.f);
}

// ---- planes [B,96,H,W] -> [B,32,H,W] float4 (plane-major texels) ----
__global__ void k_transpose(const float* __restrict__ planes){
    int i = blockIdx.x*blockDim.x + threadIdx.x;
    if (i >= BB*NPL*HH*HH) return;
    int x  = i & 63; int t = i >> 6;
    int yy = t & 63; t >>= 6;
    int kk = t & 31; int b = t >> 5;
    float4 v;
    v.x = planes[((b*96 + 3*kk+0)*HH + yy)*HH + x];
    v.y = planes[((b*96 + 3*kk+1)*HH + yy)*HH + x];
    v.z = planes[((b*96 + 3*kk+2)*HH + yy)*HH + x];
    v.w = 0.f;
    reinterpret_cast<float4*>(g_planesP)[i] = v;
}

// ---- fused feature gather + MLP: one lane = one point ----
// coarse pass (scol0==0): computes depth from noise in-register, stores it,
// and does the global depth min/max (fine depths are convex combos of coarse
// bin edges, so the coarse range IS the global range).
__global__ void __launch_bounds__(128, 4) k_pass(const float* __restrict__ ro,
                                                 const float* __restrict__ rd,
                                                 const float* __restrict__ noise,
                                                 int scol0){
    __shared__ __align__(16) float sPoses[NPL*12];
    int tid = threadIdx.x;
    for (int i = tid; i < NPL*12; i += 128) sPoses[i] = g_poses[i];
    __syncthreads();

    int q = blockIdx.x*128 + tid;                 // point index, samples fastest
    int b   = q / (NN*DD);
    int rem = q - b*(NN*DD);
    int n   = rem / DD;
    int s   = rem - n*DD;
    int ray = b*NN + n;
    int base = ray*STOT + scol0 + s;

    float depth;
    if (scol0 == 0){
        const float step = (2.5f - 0.5f)/(float)(DD-1);
        depth = 0.5f + (float)s*step + noise[q]*step;
        g_depths[base] = depth;
        warp_minmax_atomic(depth);
    } else {
        depth = g_depths[base];
    }
    float ox = ro[ray*3+0], oy = ro[ray*3+1], oz = ro[ray*3+2];
    float dx = rd[ray*3+0], dy = rd[ray*3+1], dz = rd[ray*3+2];
    float px = fmaf(depth,dx,ox), py = fmaf(depth,dy,oy), pz = fmaf(depth,dz,oz);
    const float4* planeB = reinterpret_cast<const float4*>(g_planesP) + b*(NPL*HH*HH);

    u64 acc[32];
    {
        const ulonglong2* b2 = reinterpret_cast<const ulonglong2*>(cB1f);
        #pragma unroll
        for (int p=0;p<16;p++){ ulonglong2 bp = b2[p]; acc[2*p] = bp.x; acc[2*p+1] = bp.y; }
    }

    #pragma unroll 1
    for (int kk=0; kk<NPL; kk++){
        const float* P = sPoses + kk*12;
        float cx = fmaf(P[0],px, fmaf(P[1],py, fmaf(P[2],pz,  P[3])));
        float cy = fmaf(P[4],px, fmaf(P[5],py, fmaf(P[6],pz,  P[7])));
        float cz = fmaf(P[8],px, fmaf(P[9],py, fmaf(P[10],pz, P[11])));
        float rz = __fdividef(1.f, cz);           // fast rcp: 1 div -> 2 muls below
        float gx = fminf(fmaxf(fmaf(1.0254f*cx, rz, 0.5f), 0.f), 1.f)*2.f - 1.f;
        float gy = fminf(fmaxf(fmaf(1.0254f*cy, rz, 0.5f), 0.f), 1.f)*2.f - 1.f;
        float ix = ((gx + 1.f)*(float)HH - 1.f)*0.5f;
        float iy = ((gy + 1.f)*(float)HH - 1.f)*0.5f;
        float x0 = floorf(ix), y0 = floorf(iy);
        float wx = ix - x0,    wy = iy - y0;
        float vx0 = (x0 >= 0.f)  ? 1.f : 0.f;
        float vx1 = (x0 <= 62.f) ? 1.f : 0.f;
        float vy0 = (y0 >= 0.f)  ? 1.f : 0.f;
        float vy1 = (y0 <= 62.f) ? 1.f : 0.f;
        int x0i = (int)x0, y0i = (int)y0;
        int x0c = max(x0i, 0),   y0c = max(y0i, 0);
        int x1c = min(x0i+1,63), y1c = min(y0i+1,63);
        float w00 = (1.f-wx)*(1.f-wy)*vx0*vy0;
        float w10 = wx*(1.f-wy)*vx1*vy0;
        float w01 = (1.f-wx)*wy*vx0*vy1;
        float w11 = wx*wy*vx1*vy1;
        const float4* planeK = planeB + kk*(HH*HH);
        float4 t00 = planeK[y0c*HH + x0c];
        float4 t10 = planeK[y0c*HH + x1c];
        float4 t01 = planeK[y1c*HH + x0c];
        float4 t11 = planeK[y1c*HH + x1c];

        {
            u64 ff = packf2(gx);
            const ulonglong2* w2 = reinterpret_cast<const ulonglong2*>(&cW1f[(96+2*kk)*HID]);
            #pragma unroll
            for (int p=0;p<16;p++){ ulonglong2 wp = w2[p]; ffma2(acc[2*p],ff,wp.x); ffma2(acc[2*p+1],ff,wp.y); }
        }
        {
            u64 ff = packf2(gy);
            const ulonglong2* w2 = reinterpret_cast<const ulonglong2*>(&cW1f[(96+2*kk+1)*HID]);
            #pragma unroll
            for (int p=0;p<16;p++){ ulonglong2 wp = w2[p]; ffma2(acc[2*p],ff,wp.x); ffma2(acc[2*p+1],ff,wp.y); }
        }
        float c0 = t00.x*w00 + t10.x*w10 + t01.x*w01 + t11.x*w11;
        float c1 = t00.y*w00 + t10.y*w10 + t01.y*w01 + t11.y*w11;
        float c2 = t00.z*w00 + t10.z*w10 + t01.z*w01 + t11.z*w11;
        {
            u64 ff = packf2(c0);
            const ulonglong2* w2 = reinterpret_cast<const ulonglong2*>(&cW1f[(3*kk+0)*HID]);
            #pragma unroll
            for (int p=0;p<16;p++){ ulonglong2 wp = w2[p]; ffma2(acc[2*p],ff,wp.x); ffma2(acc[2*p+1],ff,wp.y); }
        }
        {
            u64 ff = packf2(c1);
            const ulonglong2* w2 = reinterpret_cast<const ulonglong2*>(&cW1f[(3*kk+1)*HID]);
            #pragma unroll
            for (int p=0;p<16;p++){ ulonglong2 wp = w2[p]; ffma2(acc[2*p],ff,wp.x); ffma2(acc[2*p+1],ff,wp.y); }
        }
        {
            u64 ff = packf2(c2);
            const ulonglong2* w2 = reinterpret_cast<const ulonglong2*>(&cW1f[(3*kk+2)*HID]);
            #pragma unroll
            for (int p=0;p<16;p++){ ulonglong2 wp = w2[p]; ffma2(acc[2*p],ff,wp.x); ffma2(acc[2*p+1],ff,wp.y); }
        }
    }

    // layer 2 + decode, fully in registers (W2 via constant port)
    u64 acc2[17];
    #pragma unroll
    for (int p=0;p<17;p++) acc2[p] = cB2p[p];
    #pragma unroll
    for (int jh=0; jh<32; jh++){
        float a, bb;
        unpack2(acc[jh], a, bb);
        {
            u64 ha = packf2(softplus_fast(a));
            const ulonglong2* w2 = reinterpret_cast<const ulonglong2*>(&cW2p[(2*jh)*18]);
            #pragma unroll
            for (int p=0;p<8;p++){ ulonglong2 wp = w2[p]; ffma2(acc2[2*p],ha,wp.x); ffma2(acc2[2*p+1],ha,wp.y); }
            ffma2(acc2[16], ha, cW2p[(2*jh)*18 + 16]);
        }
        {
            u64 hb = packf2(softplus_fast(bb));
            const ulonglong2* w2 = reinterpret_cast<const ulonglong2*>(&cW2p[(2*jh+1)*18]);
            #pragma unroll
            for (int p=0;p<8;p++){ ulonglong2 wp = w2[p]; ffma2(acc2[2*p],hb,wp.x); ffma2(acc2[2*p+1],hb,wp.y); }
            ffma2(acc2[16], hb, cW2p[(2*jh+1)*18 + 16]);
        }
    }

    float ov[34];
    #pragma unroll
    for (int p=0;p<17;p++) unpack2(acc2[p], ov[2*p], ov[2*p+1]);
    g_sigma[base] = ov[0];
    float4* cdst = reinterpret_cast<float4*>(g_colors + (size_t)base*NCH);
    #pragma unroll
    for (int t=0;t<8;t++){
        float4 v;
        v.x = decode_rgb_fast(ov[1+4*t+0]);
        v.y = decode_rgb_fast(ov[1+4*t+1]);
        v.z = decode_rgb_fast(ov[1+4*t+2]);
        v.w = decode_rgb_fast(ov[1+4*t+3]);
        cdst[t] = v;
    }
}

// ---- fused coarse march + pdf smoothing + cdf (per-ray, weights stay in regs) ----
__global__ void k_cmarch_cdf(){
    int ray = blockIdx.x*blockDim.x + threadIdx.x;
    if (ray >= RR) return;
    const float* dep = g_depths + ray*STOT;
    const float* sig = g_sigma  + ray*STOT;
    float w[DD-1];
    float T = 1.f;
    float sp = sig[0], dp = dep[0];
    #pragma unroll 1
    for (int s=1; s<DD; s++){
        float sc = sig[s], dc = dep[s];
        float delta = dc - dp;
        float dm = softplusf(0.5f*(sp+sc) - 1.f);
        float alpha = 1.f - expf(-dm*delta);
        w[s-1] = alpha*T;
        T *= (1.f - alpha + 1e-10f);
        sp = sc; dp = dc;
    }
    float m[DD];
    m[0] = w[0]; m[DD-1] = w[DD-2];
    #pragma unroll 1
    for (int i=1;i<DD-1;i++) m[i] = fmaxf(w[i-1], w[i]);
    float pw[MIMP]; float tot = 0.f;
    #pragma unroll 1
    for (int i=0;i<MIMP;i++){
        pw[i] = 0.5f*(m[i+1] + m[i+2]) + 0.01f + 1e-5f;
        tot += pw[i];
    }
    float* cdf = g_cdf + ray*(MIMP+1);
    cdf[0] = 0.f;
    float run = 0.f;
    #pragma unroll 1
    for (int i=0;i<MIMP;i++){ run += pw[i]/tot; cdf[i+1] = run; }
}

// per-sample: searchsorted-right (upper_bound) + interp
// (no minmax here: fine depths are inside the coarse depth range by construction)
__global__ void k_sample(const float* __restrict__ u){
    int idx = blockIdx.x*blockDim.x + threadIdx.x;
    if (idx >= RR*NIMP) return;
    int ray = idx / NIMP, t = idx - ray*NIMP;
    float uu = u[idx];
    const float* cdf = g_cdf + ray*(MIMP+1);
    int lo = 0, hi = MIMP+1;           // first index with cdf[i] > u
    while (lo < hi){
        int mid = (lo + hi) >> 1;
        if (cdf[mid] <= uu) lo = mid + 1; else hi = mid;
    }
    int ind = lo;
    int below = max(ind-1, 0);
    int above = min(ind, MIMP);
    float cb = cdf[below], ca = cdf[above];
    const float* z = g_depths + ray*STOT;
    float bb = z[below], ba = z[above];
    float denom = ca - cb;
    if (denom < 1e-5f) denom = 1.f;
    g_depths[ray*STOT + DD + t] = bb + (uu - cb)/denom*(ba - bb);
}

// ---- parallel stable-merge order: one thread per (ray, sample) ----
__global__ void k_order(){
    int idx = blockIdx.x*blockDim.x + threadIdx.x;
    if (idx >= RR*STOT) return;
    int ray = idx / STOT, i = idx - ray*STOT;
    const float* dep = g_depths + ray*STOT;
    int pos;
    if (i < DD){
        float z = dep[i];
        int cnt = 0;
        #pragma unroll 1
        for (int j=0;j<NIMP;j++) cnt += (dep[DD+j] < z) ? 1 : 0;
        pos = i + cnt;
    } else {
        int t = i - DD;
        float z = dep[i];
        int cc = 0;
        #pragma unroll 1
        for (int s=0;s<DD;s++) cc += (dep[s] <= z) ? 1 : 0;
        int cf = 0;
        #pragma unroll 1
        for (int j=0;j<NIMP;j++){
            float zj = dep[DD+j];
            cf += (zj < z || (zj == z && j < t)) ? 1 : 0;
        }
        pos = cc + cf;
    }
    g_sidx[ray*STOT + pos] = (unsigned char)i;
}

// ---- final march over precomputed order ----
__global__ void k_march(float* __restrict__ out){
    int ray = blockIdx.x*blockDim.x + threadIdx.x;
    if (ray >= RR) return;
    const float* dep = g_depths + ray*STOT;
    const float* sig = g_sigma  + ray*STOT;
    const unsigned char* ord = g_sidx + ray*STOT;
    float T = 1.f, wtot = 0.f, dsum = 0.f;
    int ip = ord[0];
    float dprev = dep[ip], sp = sig[ip];
    #pragma unroll 1
    for (int s=1;s<STOT;s++){
        int ic = ord[s];
        float dc = dep[ic], sc = sig[ic];
        float delta = dc - dprev;
        float dm = softplusf(0.5f*(sp+sc) - 1.f);
        float alpha = 1.f - expf(-dm*delta);
        float wgt = alpha*T;
        g_wf[ray*(STOT-1) + s-1] = wgt;
        wtot += wgt;
        dsum += wgt*0.5f*(dprev + dc);
        T *= (1.f - alpha + 1e-10f);
        dprev = dc; sp = sc;
    }
    float depth = dsum/wtot;
    if (isnan(depth)) depth = __int_as_float(0x7f800000);
    float dmin = __uint_as_float(g_dmin_bits), dmax = __uint_as_float(g_dmax_bits);
    depth = fminf(fmaxf(depth, dmin), dmax);
    out[ray*34 + 32] = depth;
    out[ray*34 + 33] = wtot;
}

// channel-vectorized rgb: one thread = 4 channels of one ray
__global__ void k_rgb(float* __restrict__ out){
    int idx = blockIdx.x*blockDim.x + threadIdx.x;
    if (idx >= RR*8) return;
    int c4 = (idx & 7); int ray = idx >> 3;
    const unsigned char* mi = g_sidx + ray*STOT;
    const float4* col = reinterpret_cast<const float4*>(g_colors + (size_t)ray*STOT*NCH);
    const float* wv  = g_wf + ray*(STOT-1);
    float4 acc = make_float4(0.f,0.f,0.f,0.f);
    float4 cp = col[(int)mi[0]*8 + c4];
    #pragma unroll 1
    for (int s=1;s<STOT;s++){
        float4 cc = col[(int)mi[s]*8 + c4];
        float w = wv[s-1]*0.5f;
        acc.x += w*(cp.x + cc.x);
        acc.y += w*(cp.y + cc.y);
        acc.z += w*(cp.z + cc.z);
        acc.w += w*(cp.w + cc.w);
        cp = cc;
    }
    float* o = out + ray*34 + c4*4;
    o[0] = acc.x*2.f - 1.f;
    o[1] = acc.y*2.f - 1.f;
    o[2] = acc.z*2.f - 1.f;
    o[3] = acc.w*2.f - 1.f;
}

extern "C" void kernel_launch(void* const* d_in, const int* in_sizes, int n_in,
                              void* d_out, int out_size){
    const float* planes = (const float*)d_in[0];
    const float* ro     = (const float*)d_in[1];
    const float* rd     = (const float*)d_in[2];
    const float* noise  = (const float*)d_in[3];
    const float* pdfu   = (const float*)d_in[4];
    const float* W2g    = (const float*)d_in[7];
    const float* B2g    = (const float*)d_in[8];
    float* out = (float*)d_out;

    cudaMemcpyToSymbolAsync(cW1f, d_in[5], FD*HID*sizeof(float), 0, cudaMemcpyDeviceToDevice, 0);
    cudaMemcpyToSymbolAsync(cB1f, d_in[6], HID*sizeof(float),    0, cudaMemcpyDeviceToDevice, 0);

    // pack W2/B2 on device, then stage into constant memory
    k_prepW2<<<(HID*18 + 127)/128, 128>>>(W2g, B2g);
    {
        void* pW2 = nullptr; void* pB2 = nullptr;
        cudaGetSymbolAddress(&pW2, g_W2p);
        cudaGetSymbolAddress(&pB2, g_B2p);
        cudaMemcpyToSymbolAsync(cW2p, pW2, HID*18*sizeof(u64), 0, cudaMemcpyDeviceToDevice, 0);
        cudaMemcpyToSymbolAsync(cB2p, pB2, 17*sizeof(u64),     0, cudaMemcpyDeviceToDevice, 0);
    }

    k_poses<<<1, 32>>>();
    k_transpose<<<(BB*NPL*HH*HH + 255)/256, 256>>>(planes);

    // coarse pass (computes + stores coarse depths and the global depth range)
    k_pass<<<(RR*DD)/128, 128>>>(ro, rd, noise, 0);
    k_cmarch_cdf<<<(RR + 63)/64, 64>>>();
    k_sample<<<(RR*NIMP + 255)/256, 256>>>(pdfu);

    // fine pass (NIMP == DD so the same index math applies)
    k_pass<<<(RR*NIMP)/128, 128>>>(ro, rd, noise, DD);

    // merged order + final march + rgb
    k_order<<<(RR*STOT + 255)/256, 256>>>();
    k_march<<<(RR + 63)/64, 64>>>(out);
    k_rgb<<<(RR*8 + 127)/128, 128>>>(out);
}